// round 4
// baseline (speedup 1.0000x reference)
#include <cuda_runtime.h>
#include <math.h>

#define T_LEN 2048
#define DIM   768
#define NH    12
#define HD    64

// ---------------- scratch (no allocation allowed) ----------------
__device__ float g_q[T_LEN * DIM];
__device__ float g_k[T_LEN * DIM];
__device__ float g_v[T_LEN * DIM];
__device__ float g_y[T_LEN * DIM];

// ---------------- common tensor-core helpers ----------------
__device__ __forceinline__ unsigned f2tf32(float f) {
    unsigned u;
    asm("cvt.rna.tf32.f32 %0, %1;" : "=r"(u) : "f"(f));
    return u;
}

__device__ __forceinline__ void mma8(float* c, const unsigned* a, const unsigned* b) {
    asm volatile(
        "mma.sync.aligned.m16n8k8.row.col.f32.tf32.tf32.f32 "
        "{%0,%1,%2,%3}, {%4,%5,%6,%7}, {%8,%9}, {%0,%1,%2,%3};\n"
        : "+f"(c[0]), "+f"(c[1]), "+f"(c[2]), "+f"(c[3])
        : "r"(a[0]), "r"(a[1]), "r"(a[2]), "r"(a[3]), "r"(b[0]), "r"(b[1]));
}

__device__ __forceinline__ void cp16(void* smem_dst, const void* gsrc) {
    unsigned d = (unsigned)__cvta_generic_to_shared(smem_dst);
    asm volatile("cp.async.ca.shared.global [%0], [%1], 16;\n" :: "r"(d), "l"(gsrc));
}

// =====================================================================
// tf32 tensor-core GEMM:  C = A @ B^T   (A [M,K], B [N,K], C [M,N])
// CTA tile 64x64, 128 threads (4 warps 2x2), warp tile 32x32.
// K-chunk 32, 2-stage cp.async double buffer.
// blockIdx.z selects (W,C); z==2 + addsrc: C = (1-lamb)*A@B^T + lamb*addsrc.
// do_normrope: for z<2, apply per-head RMSNorm + RoPE in the epilogue
// (valid because the 64-col N-tile is exactly one head).
// =====================================================================
#define GBK 32
#define GST 36                              // smem row stride (36 % 32 == 4)
#define STG_FLOATS (2 * 64 * GST)           // A + B per stage = 4608 floats
#define GEMM_SMEM_BYTES (2 * STG_FLOATS * 4)  // 36864

__global__ __launch_bounds__(128)
void gemm_tf32(const float* __restrict__ A,
               const float* __restrict__ W0, const float* __restrict__ W1,
               const float* __restrict__ W2,
               float* __restrict__ C0, float* __restrict__ C1, float* __restrict__ C2,
               const float* __restrict__ addsrc, const float* __restrict__ lamb_ptr,
               int do_normrope, int M, int N, int K)
{
    extern __shared__ float sm[];

    const int z = blockIdx.z;
    const float* B = (z == 0) ? W0 : (z == 1) ? W1 : W2;
    float*       C = (z == 0) ? C0 : (z == 1) ? C1 : C2;

    const int tid  = threadIdx.x;
    const int lane = tid & 31;
    const int warp = tid >> 5;
    const int wm   = warp >> 1;        // 0..1
    const int wn   = warp & 1;         // 0..1
    const int bm   = blockIdx.y * 64;
    const int bn   = blockIdx.x * 64;
    const int gr   = lane >> 2;
    const int tig  = lane & 3;

    // loader: thread t loads one full 32-float row (A for t<64, B for t>=64)
    const int ld_mat = tid >> 6;
    const int ld_row = tid & 63;
    const float* ld_src = (ld_mat ? B + (size_t)(bn + ld_row) * K
                                  : A + (size_t)(bm + ld_row) * K);

    float acc[2][4][4];
#pragma unroll
    for (int mi = 0; mi < 2; mi++)
#pragma unroll
        for (int ni = 0; ni < 4; ni++)
#pragma unroll
            for (int r = 0; r < 4; r++) acc[mi][ni][r] = 0.f;

    const int nt = K / GBK;            // 24

#define G_LOAD(T, STG) do {                                                    \
        float* dst = sm + (STG) * STG_FLOATS + ld_mat * 64 * GST + ld_row * GST; \
        const float* src = ld_src + (T) * GBK;                                 \
        _Pragma("unroll")                                                      \
        for (int i_ = 0; i_ < 8; i_++) cp16(dst + i_ * 4, src + i_ * 4);       \
    } while (0)

    G_LOAD(0, 0);
    asm volatile("cp.async.commit_group;\n");

    for (int t = 0; t < nt; t++) {
        if (t + 1 < nt) {
            G_LOAD(t + 1, (t + 1) & 1);
            asm volatile("cp.async.commit_group;\n");
            asm volatile("cp.async.wait_group 1;\n");
        } else {
            asm volatile("cp.async.wait_group 0;\n");
        }
        __syncthreads();

        const float* As = sm + (t & 1) * STG_FLOATS;
        const float* Bs = As + 64 * GST;

#pragma unroll
        for (int ks = 0; ks < 4; ks++) {
            const int kk = ks * 8;
            unsigned a[2][4], b[4][2];
#pragma unroll
            for (int mi = 0; mi < 2; mi++) {
                const int r = wm * 32 + mi * 16 + gr;
                const int c = kk + tig;
                a[mi][0] = f2tf32(As[r * GST + c]);
                a[mi][1] = f2tf32(As[(r + 8) * GST + c]);
                a[mi][2] = f2tf32(As[r * GST + c + 4]);
                a[mi][3] = f2tf32(As[(r + 8) * GST + c + 4]);
            }
#pragma unroll
            for (int ni = 0; ni < 4; ni++) {
                const int n = wn * 32 + ni * 8 + gr;
                b[ni][0] = f2tf32(Bs[n * GST + kk + tig]);
                b[ni][1] = f2tf32(Bs[n * GST + kk + 4 + tig]);
            }
#pragma unroll
            for (int mi = 0; mi < 2; mi++)
#pragma unroll
                for (int ni = 0; ni < 4; ni++)
                    mma8(acc[mi][ni], a[mi], b[ni]);
        }
        __syncthreads();
    }

    if (do_normrope && z < 2) {
        // ---- stage acc tile into smem [64][68] ----
        float* st = sm;
#pragma unroll
        for (int mi = 0; mi < 2; mi++)
#pragma unroll
            for (int ni = 0; ni < 4; ni++) {
                const int r0 = wm * 32 + mi * 16 + gr;
                const int c0 = wn * 32 + ni * 8 + tig * 2;
                *(float2*)&st[r0 * 68 + c0]       = make_float2(acc[mi][ni][0], acc[mi][ni][1]);
                *(float2*)&st[(r0 + 8) * 68 + c0] = make_float2(acc[mi][ni][2], acc[mi][ni][3]);
            }
        __syncthreads();

        // ---- per-row RMSNorm + RoPE; 2 threads per row ----
        const int r    = tid >> 1;
        const int half = tid & 1;
        const float* row = st + r * 68;

        float x1[16], x2[16];
        float ss = 0.f;
#pragma unroll
        for (int i4 = 0; i4 < 4; i4++) {
            float4 u = *(const float4*)&row[half * 16 + i4 * 4];
            float4 w = *(const float4*)&row[half * 16 + i4 * 4 + 32];
            x1[i4 * 4 + 0] = u.x; x1[i4 * 4 + 1] = u.y; x1[i4 * 4 + 2] = u.z; x1[i4 * 4 + 3] = u.w;
            x2[i4 * 4 + 0] = w.x; x2[i4 * 4 + 1] = w.y; x2[i4 * 4 + 2] = w.z; x2[i4 * 4 + 3] = w.w;
            ss += u.x * u.x + u.y * u.y + u.z * u.z + u.w * u.w;
            ss += w.x * w.x + w.y * w.y + w.z * w.z + w.w * w.w;
        }
        ss += __shfl_xor_sync(0xffffffffu, ss, 1);
        const float rn = rsqrtf(ss * (1.f / 64.f) + 1.1920929e-07f);

        const int tok = bm + r;
        float o1[16], o2[16];
#pragma unroll
        for (int i = 0; i < 16; i++) {
            const int j = half * 16 + i;
            const float inv = expf(-(float)j * 0.28782313662425572f); // ln(1e4)/32
            const float ang = (float)tok * inv;
            const float c = cosf(ang);
            const float s = sinf(ang);
            const float a1 = x1[i] * rn, a2 = x2[i] * rn;
            o1[i] =  a1 * c + a2 * s;
            o2[i] = -a1 * s + a2 * c;
        }
        float* Crow = C + (size_t)tok * N + bn;
#pragma unroll
        for (int i4 = 0; i4 < 4; i4++) {
            *(float4*)&Crow[half * 16 + i4 * 4]      = make_float4(o1[i4*4], o1[i4*4+1], o1[i4*4+2], o1[i4*4+3]);
            *(float4*)&Crow[half * 16 + i4 * 4 + 32] = make_float4(o2[i4*4], o2[i4*4+1], o2[i4*4+2], o2[i4*4+3]);
        }
        return;
    }

    // ---- plain / blended store ----
    const bool blend = (z == 2) && (addsrc != nullptr);
    const float lb = blend ? *lamb_ptr : 0.f;
    const float om = 1.f - lb;

#pragma unroll
    for (int mi = 0; mi < 2; mi++) {
#pragma unroll
        for (int ni = 0; ni < 4; ni++) {
            const int r0 = bm + wm * 32 + mi * 16 + gr;
            const int c0 = bn + wn * 32 + ni * 8 + tig * 2;
            float2 v0 = make_float2(acc[mi][ni][0], acc[mi][ni][1]);
            float2 v1 = make_float2(acc[mi][ni][2], acc[mi][ni][3]);
            if (blend) {
                const float* s0 = addsrc + (size_t)r0 * N + c0;
                const float* s1 = addsrc + (size_t)(r0 + 8) * N + c0;
                v0.x = om * v0.x + lb * s0[0];
                v0.y = om * v0.y + lb * s0[1];
                v1.x = om * v1.x + lb * s1[0];
                v1.y = om * v1.y + lb * s1[1];
            }
            *(float2*)(C + (size_t)r0 * N + c0)       = v0;
            *(float2*)(C + (size_t)(r0 + 8) * N + c0) = v1;
        }
    }
}

// =====================================================================
// tensor-core causal flash attention (tf32 MMA, fixed-shift softmax)
// =====================================================================
#define AKSTR 68
#define AVSTR 72
#define AT_K_OFF 0
#define AT_V_OFF (2 * 64 * AKSTR)
#define AT_P_OFF (AT_V_OFF + 2 * 64 * AVSTR)
#define ATTN_SMEM_FLOATS (AT_P_OFF + 64 * AKSTR)
#define ATTN_SMEM_BYTES  (ATTN_SMEM_FLOATS * 4)   // 89088

__global__ __launch_bounds__(128)
void attn_tc_kernel(const float* __restrict__ q, const float* __restrict__ k,
                    const float* __restrict__ v, float* __restrict__ y)
{
    extern __shared__ float sm[];
    float* k_s = sm + AT_K_OFF;
    float* v_s = sm + AT_V_OFF;
    float* p_s = sm + AT_P_OFF;

    const int h   = blockIdx.x;
    const int qb  = (gridDim.y - 1) - blockIdx.y;
    const int q0  = qb * 64;
    const int tid = threadIdx.x;
    const int w    = tid >> 5;
    const int lane = tid & 31;
    const int gr   = lane >> 2;
    const int tig  = lane & 3;
    const int wrow = w * 16;

    unsigned aq[8][4];
    {
        const float* qb_ = q + (size_t)(q0 + wrow) * DIM + h * HD;
#pragma unroll
        for (int ks = 0; ks < 8; ks++) {
            const int c = ks * 8 + tig;
            aq[ks][0] = f2tf32(0.125f * qb_[(size_t)gr * DIM + c]);
            aq[ks][1] = f2tf32(0.125f * qb_[(size_t)(gr + 8) * DIM + c]);
            aq[ks][2] = f2tf32(0.125f * qb_[(size_t)gr * DIM + c + 4]);
            aq[ks][3] = f2tf32(0.125f * qb_[(size_t)(gr + 8) * DIM + c + 4]);
        }
    }

    float oacc[8][4];
#pragma unroll
    for (int ni = 0; ni < 8; ni++)
#pragma unroll
        for (int r = 0; r < 4; r++) oacc[ni][r] = 0.f;
    float l0 = 0.f, l1 = 0.f;

    const int ld_row = tid >> 1;
    const int ld_c0  = (tid & 1) * 32;
#define LOAD_KV(KB, STG) do {                                                  \
        const float* kg = k + (size_t)((KB) * 64 + ld_row) * DIM + h * HD + ld_c0; \
        const float* vg = v + (size_t)((KB) * 64 + ld_row) * DIM + h * HD + ld_c0; \
        float* kd = k_s + (STG) * 64 * AKSTR + ld_row * AKSTR + ld_c0;         \
        float* vd = v_s + (STG) * 64 * AVSTR + ld_row * AVSTR + ld_c0;         \
        _Pragma("unroll")                                                      \
        for (int i_ = 0; i_ < 8; i_++) {                                       \
            cp16(kd + i_ * 4, kg + i_ * 4);                                    \
            cp16(vd + i_ * 4, vg + i_ * 4);                                    \
        }                                                                      \
    } while (0)

    LOAD_KV(0, 0);
    asm volatile("cp.async.commit_group;\n");

    for (int kb = 0; kb <= qb; kb++) {
        if (kb < qb) {
            LOAD_KV(kb + 1, (kb + 1) & 1);
            asm volatile("cp.async.commit_group;\n");
            asm volatile("cp.async.wait_group 1;\n");
        } else {
            asm volatile("cp.async.wait_group 0;\n");
        }
        __syncthreads();

        const float* ks_ = k_s + (kb & 1) * 64 * AKSTR;
        const float* vs_ = v_s + (kb & 1) * 64 * AVSTR;

        float s[8][4];
#pragma unroll
        for (int ni = 0; ni < 8; ni++)
#pragma unroll
            for (int r = 0; r < 4; r++) s[ni][r] = 0.f;

#pragma unroll
        for (int ni = 0; ni < 8; ni++) {
            const float* kr = ks_ + (ni * 8 + gr) * AKSTR + tig;
#pragma unroll
            for (int ks = 0; ks < 8; ks++) {
                unsigned b[2];
                b[0] = f2tf32(kr[ks * 8]);
                b[1] = f2tf32(kr[ks * 8 + 4]);
                mma8(s[ni], aq[ks], b);
            }
        }

        const bool diag = (kb == qb);
        const int r0 = wrow + gr, r1 = r0 + 8;
#pragma unroll
        for (int ni = 0; ni < 8; ni++) {
            const int c0 = ni * 8 + 2 * tig;
            float p0 = __expf(s[ni][0] - 8.f);
            float p1 = __expf(s[ni][1] - 8.f);
            float p2 = __expf(s[ni][2] - 8.f);
            float p3 = __expf(s[ni][3] - 8.f);
            if (diag) {
                if (c0 > r0)     p0 = 0.f;
                if (c0 + 1 > r0) p1 = 0.f;
                if (c0 > r1)     p2 = 0.f;
                if (c0 + 1 > r1) p3 = 0.f;
            }
            l0 += p0 + p1;
            l1 += p2 + p3;
            uint2 w0; w0.x = f2tf32(p0); w0.y = f2tf32(p1);
            uint2 w1; w1.x = f2tf32(p2); w1.y = f2tf32(p3);
            *(uint2*)&p_s[r0 * AKSTR + c0] = w0;
            *(uint2*)&p_s[r1 * AKSTR + c0] = w1;
        }
        __syncwarp();

        const unsigned* pu = (const unsigned*)p_s;
#pragma unroll
        for (int ks = 0; ks < 8; ks++) {
            unsigned ap[4];
            ap[0] = pu[r0 * AKSTR + ks * 8 + tig];
            ap[1] = pu[r1 * AKSTR + ks * 8 + tig];
            ap[2] = pu[r0 * AKSTR + ks * 8 + 4 + tig];
            ap[3] = pu[r1 * AKSTR + ks * 8 + 4 + tig];
            const float* vr = vs_ + (ks * 8 + tig) * AVSTR + gr;
#pragma unroll
            for (int ni = 0; ni < 8; ni++) {
                unsigned b[2];
                b[0] = f2tf32(vr[ni * 8]);
                b[1] = f2tf32(vr[4 * AVSTR + ni * 8]);
                mma8(oacc[ni], ap, b);
            }
        }
        __syncthreads();
    }

    l0 += __shfl_xor_sync(0xffffffffu, l0, 1);
    l0 += __shfl_xor_sync(0xffffffffu, l0, 2);
    l1 += __shfl_xor_sync(0xffffffffu, l1, 1);
    l1 += __shfl_xor_sync(0xffffffffu, l1, 2);
    const float inv0 = 1.f / l0;
    const float inv1 = 1.f / l1;

    const int r0 = wrow + gr;
#pragma unroll
    for (int ni = 0; ni < 8; ni++) {
        const int c = ni * 8 + 2 * tig;
        float2 o0 = make_float2(oacc[ni][0] * inv0, oacc[ni][1] * inv0);
        float2 o1 = make_float2(oacc[ni][2] * inv1, oacc[ni][3] * inv1);
        *(float2*)&y[(size_t)(q0 + r0) * DIM + h * HD + c]     = o0;
        *(float2*)&y[(size_t)(q0 + r0 + 8) * DIM + h * HD + c] = o1;
    }
}

// ---------------- launch ----------------
extern "C" void kernel_launch(void* const* d_in, const int* in_sizes, int n_in,
                              void* d_out, int out_size)
{
    const float* x    = (const float*)d_in[0];
    const float* vi   = (const float*)d_in[1];
    const float* Wq   = (const float*)d_in[2];
    const float* Wk   = (const float*)d_in[3];
    const float* Wv   = (const float*)d_in[4];
    const float* Wp   = (const float*)d_in[5];
    const float* lamb = (const float*)d_in[6];
    float* out = (float*)d_out;

    float *q, *k, *v, *y;
    cudaGetSymbolAddress((void**)&q, g_q);
    cudaGetSymbolAddress((void**)&k, g_k);
    cudaGetSymbolAddress((void**)&v, g_v);
    cudaGetSymbolAddress((void**)&y, g_y);

    cudaFuncSetAttribute(gemm_tf32, cudaFuncAttributeMaxDynamicSharedMemorySize,
                         GEMM_SMEM_BYTES);
    cudaFuncSetAttribute(attn_tc_kernel, cudaFuncAttributeMaxDynamicSharedMemorySize,
                         ATTN_SMEM_BYTES);

    // fused QKV GEMM: z=0/1 -> Q/K with fused RMSNorm+RoPE, z=2 -> V blended
    dim3 gqkv(DIM / 64, T_LEN / 64, 3);
    gemm_tf32<<<gqkv, 128, GEMM_SMEM_BYTES>>>(x, Wq, Wk, Wv, q, k, v, vi, lamb,
                                              1, T_LEN, DIM, DIM);

    // tensor-core causal attention
    dim3 gattn(NH, T_LEN / 64);
    attn_tc_kernel<<<gattn, 128, ATTN_SMEM_BYTES>>>(q, k, v, y);

    // output projection
    dim3 gproj(DIM / 64, T_LEN / 64, 1);
    gemm_tf32<<<gproj, 128, GEMM_SMEM_BYTES>>>(y, Wp, Wp, Wp, out, out, out,
                                               nullptr, nullptr, 0, T_LEN, DIM, DIM);
}

// round 5
// speedup vs baseline: 1.6092x; 1.6092x over previous
#include <cuda_runtime.h>
#include <math.h>

#define T_LEN 2048
#define DIM   768
#define NH    12
#define HD    64

// ---------------- scratch (no allocation allowed) ----------------
__device__ float g_q[T_LEN * DIM];
__device__ float g_k[T_LEN * DIM];
__device__ float g_v[T_LEN * DIM];
__device__ float g_y[T_LEN * DIM];

// ---------------- common tensor-core helpers ----------------
__device__ __forceinline__ unsigned f2tf32(float f) {
    unsigned u;
    asm("cvt.rna.tf32.f32 %0, %1;" : "=r"(u) : "f"(f));
    return u;
}

__device__ __forceinline__ void mma8(float* c, const unsigned* a, const unsigned* b) {
    asm volatile(
        "mma.sync.aligned.m16n8k8.row.col.f32.tf32.tf32.f32 "
        "{%0,%1,%2,%3}, {%4,%5,%6,%7}, {%8,%9}, {%0,%1,%2,%3};\n"
        : "+f"(c[0]), "+f"(c[1]), "+f"(c[2]), "+f"(c[3])
        : "r"(a[0]), "r"(a[1]), "r"(a[2]), "r"(a[3]), "r"(b[0]), "r"(b[1]));
}

__device__ __forceinline__ void cp16(void* smem_dst, const void* gsrc) {
    unsigned d = (unsigned)__cvta_generic_to_shared(smem_dst);
    asm volatile("cp.async.ca.shared.global [%0], [%1], 16;\n" :: "r"(d), "l"(gsrc));
}

// =====================================================================
// tf32 tensor-core GEMM:  C = A @ B^T   (A [M,K], B [N,K], C [M,N])
// CTA tile 128x128, 8 warps (2x4), warp tile 64x32. KC=32, 2-stage cp.async.
// blockIdx.z selects (W,C); z==2 + addsrc: blended V output.
// do_normrope: z<2 -> fused per-head RMSNorm + RoPE epilogue
// (128-col tile spans exactly 2 heads; thread (tid&1) owns one head-row).
// =====================================================================
#define KC      32
#define GSTRIDE 36
#define STAGE_FLOATS (2 * 128 * GSTRIDE)
#define GEMM_SMEM_BYTES (2 * STAGE_FLOATS * 4)   // 73728

__device__ __forceinline__ void load_stage(float* As, float* Bs,
                                           const float* A, const float* B,
                                           int bm, int bn, int k0, int K, int tid)
{
    const int row = tid >> 3;
    const int col = (tid & 7) * 4;
#pragma unroll
    for (int p = 0; p < 4; p++) {
        const int r = row + p * 32;
        cp16(&As[r * GSTRIDE + col], A + (size_t)(bm + r) * K + k0 + col);
        cp16(&Bs[r * GSTRIDE + col], B + (size_t)(bn + r) * K + k0 + col);
    }
}

__global__ __launch_bounds__(256)
void gemm_tf32(const float* __restrict__ A,
               const float* __restrict__ W0, const float* __restrict__ W1,
               const float* __restrict__ W2,
               float* __restrict__ C0, float* __restrict__ C1, float* __restrict__ C2,
               const float* __restrict__ addsrc, const float* __restrict__ lamb_ptr,
               int do_normrope, int M, int N, int K)
{
    extern __shared__ float sm[];

    const int z = blockIdx.z;
    const float* B = (z == 0) ? W0 : (z == 1) ? W1 : W2;
    float*       C = (z == 0) ? C0 : (z == 1) ? C1 : C2;

    const int tid  = threadIdx.x;
    const int lane = tid & 31;
    const int warp = tid >> 5;
    const int wm   = warp >> 2;
    const int wn   = warp & 3;
    const int bm   = blockIdx.y * 128;
    const int bn   = blockIdx.x * 128;
    const int gr   = lane >> 2;
    const int tig  = lane & 3;

    float acc[4][4][4];
#pragma unroll
    for (int mi = 0; mi < 4; mi++)
#pragma unroll
        for (int ni = 0; ni < 4; ni++)
#pragma unroll
            for (int r = 0; r < 4; r++) acc[mi][ni][r] = 0.f;

    const int nt = K / KC;

    load_stage(sm, sm + 128 * GSTRIDE, A, B, bm, bn, 0, K, tid);
    asm volatile("cp.async.commit_group;\n");

    for (int t = 0; t < nt; t++) {
        if (t + 1 < nt) {
            float* dst = sm + ((t + 1) & 1) * STAGE_FLOATS;
            load_stage(dst, dst + 128 * GSTRIDE, A, B, bm, bn, (t + 1) * KC, K, tid);
            asm volatile("cp.async.commit_group;\n");
            asm volatile("cp.async.wait_group 1;\n");
        } else {
            asm volatile("cp.async.wait_group 0;\n");
        }
        __syncthreads();

        const float* As = sm + (t & 1) * STAGE_FLOATS;
        const float* Bs = As + 128 * GSTRIDE;

#pragma unroll
        for (int ks = 0; ks < 4; ks++) {
            const int kk = ks * 8;
            unsigned a[4][4], b[4][2];
#pragma unroll
            for (int mi = 0; mi < 4; mi++) {
                const int r = wm * 64 + mi * 16 + gr;
                const int c = kk + tig;
                a[mi][0] = f2tf32(As[r * GSTRIDE + c]);
                a[mi][1] = f2tf32(As[(r + 8) * GSTRIDE + c]);
                a[mi][2] = f2tf32(As[r * GSTRIDE + c + 4]);
                a[mi][3] = f2tf32(As[(r + 8) * GSTRIDE + c + 4]);
            }
#pragma unroll
            for (int ni = 0; ni < 4; ni++) {
                const int n = wn * 32 + ni * 8 + gr;
                b[ni][0] = f2tf32(Bs[n * GSTRIDE + kk + tig]);
                b[ni][1] = f2tf32(Bs[n * GSTRIDE + kk + 4 + tig]);
            }
#pragma unroll
            for (int mi = 0; mi < 4; mi++)
#pragma unroll
                for (int ni = 0; ni < 4; ni++)
                    mma8(acc[mi][ni], a[mi], b[ni]);
        }
        __syncthreads();
    }

    if (do_normrope && z < 2) {
        // ---- stage acc tile into smem [128][132] (fits in 73.7KB) ----
        float* st = sm;
#pragma unroll
        for (int mi = 0; mi < 4; mi++)
#pragma unroll
            for (int ni = 0; ni < 4; ni++) {
                const int r0 = wm * 64 + mi * 16 + gr;
                const int c0 = wn * 32 + ni * 8 + tig * 2;
                *(float2*)&st[r0 * 132 + c0]       = make_float2(acc[mi][ni][0], acc[mi][ni][1]);
                *(float2*)&st[(r0 + 8) * 132 + c0] = make_float2(acc[mi][ni][2], acc[mi][ni][3]);
            }
        __syncthreads();

        // ---- RMSNorm + RoPE: thread owns one (row, head). 2 thr/row ----
        const int r  = tid >> 1;          // 0..127
        const int hh = tid & 1;           // which head within the 128-col tile
        const float* row = st + r * 132 + hh * 64;

        float x1[32], x2[32];
        float ss = 0.f;
#pragma unroll
        for (int i4 = 0; i4 < 8; i4++) {
            float4 u = *(const float4*)&row[i4 * 4];
            float4 w = *(const float4*)&row[i4 * 4 + 32];
            x1[i4 * 4 + 0] = u.x; x1[i4 * 4 + 1] = u.y; x1[i4 * 4 + 2] = u.z; x1[i4 * 4 + 3] = u.w;
            x2[i4 * 4 + 0] = w.x; x2[i4 * 4 + 1] = w.y; x2[i4 * 4 + 2] = w.z; x2[i4 * 4 + 3] = w.w;
            ss += u.x * u.x + u.y * u.y + u.z * u.z + u.w * u.w;
            ss += w.x * w.x + w.y * w.y + w.z * w.z + w.w * w.w;
        }
        const float rn = rsqrtf(ss * (1.f / 64.f) + 1.1920929e-07f);

        const int tok = bm + r;
        float o1[32], o2[32];
#pragma unroll
        for (int j = 0; j < 32; j++) {
            const float inv = expf(-(float)j * 0.28782313662425572f); // ln(1e4)/32
            const float ang = (float)tok * inv;
            const float c = cosf(ang);
            const float s = sinf(ang);
            const float a1 = x1[j] * rn, a2 = x2[j] * rn;
            o1[j] =  a1 * c + a2 * s;
            o2[j] = -a1 * s + a2 * c;
        }
        float* Crow = C + (size_t)tok * N + bn + hh * 64;
#pragma unroll
        for (int i4 = 0; i4 < 8; i4++) {
            *(float4*)&Crow[i4 * 4]      = make_float4(o1[i4*4], o1[i4*4+1], o1[i4*4+2], o1[i4*4+3]);
            *(float4*)&Crow[i4 * 4 + 32] = make_float4(o2[i4*4], o2[i4*4+1], o2[i4*4+2], o2[i4*4+3]);
        }
        return;
    }

    // ---- plain / blended store ----
    const bool blend = (z == 2) && (addsrc != nullptr);
    const float lb = blend ? *lamb_ptr : 0.f;
    const float om = 1.f - lb;

#pragma unroll
    for (int mi = 0; mi < 4; mi++) {
#pragma unroll
        for (int ni = 0; ni < 4; ni++) {
            const int r0 = bm + wm * 64 + mi * 16 + gr;
            const int c0 = bn + wn * 32 + ni * 8 + tig * 2;
            float2 v0 = make_float2(acc[mi][ni][0], acc[mi][ni][1]);
            float2 v1 = make_float2(acc[mi][ni][2], acc[mi][ni][3]);
            if (blend) {
                const float* s0 = addsrc + (size_t)r0 * N + c0;
                const float* s1 = addsrc + (size_t)(r0 + 8) * N + c0;
                v0.x = om * v0.x + lb * s0[0];
                v0.y = om * v0.y + lb * s0[1];
                v1.x = om * v1.x + lb * s1[0];
                v1.y = om * v1.y + lb * s1[1];
            }
            *(float2*)(C + (size_t)r0 * N + c0)       = v0;
            *(float2*)(C + (size_t)(r0 + 8) * N + c0) = v1;
        }
    }
}

// =====================================================================
// tensor-core causal flash attention (tf32 MMA, fixed-shift softmax)
// CTA = (64-query block, head); 4 warps, warp owns 16 query rows.
// =====================================================================
#define AKSTR 68
#define AVSTR 72
#define AT_K_OFF 0
#define AT_V_OFF (2 * 64 * AKSTR)
#define AT_P_OFF (AT_V_OFF + 2 * 64 * AVSTR)
#define ATTN_SMEM_FLOATS (AT_P_OFF + 64 * AKSTR)
#define ATTN_SMEM_BYTES  (ATTN_SMEM_FLOATS * 4)   // 89088

__global__ __launch_bounds__(128)
void attn_tc_kernel(const float* __restrict__ q, const float* __restrict__ k,
                    const float* __restrict__ v, float* __restrict__ y)
{
    extern __shared__ float sm[];
    float* k_s = sm + AT_K_OFF;
    float* v_s = sm + AT_V_OFF;
    float* p_s = sm + AT_P_OFF;

    const int h   = blockIdx.x;
    const int qb  = (gridDim.y - 1) - blockIdx.y;
    const int q0  = qb * 64;
    const int tid = threadIdx.x;
    const int w    = tid >> 5;
    const int lane = tid & 31;
    const int gr   = lane >> 2;
    const int tig  = lane & 3;
    const int wrow = w * 16;

    unsigned aq[8][4];
    {
        const float* qb_ = q + (size_t)(q0 + wrow) * DIM + h * HD;
#pragma unroll
        for (int ks = 0; ks < 8; ks++) {
            const int c = ks * 8 + tig;
            aq[ks][0] = f2tf32(0.125f * qb_[(size_t)gr * DIM + c]);
            aq[ks][1] = f2tf32(0.125f * qb_[(size_t)(gr + 8) * DIM + c]);
            aq[ks][2] = f2tf32(0.125f * qb_[(size_t)gr * DIM + c + 4]);
            aq[ks][3] = f2tf32(0.125f * qb_[(size_t)(gr + 8) * DIM + c + 4]);
        }
    }

    float oacc[8][4];
#pragma unroll
    for (int ni = 0; ni < 8; ni++)
#pragma unroll
        for (int r = 0; r < 4; r++) oacc[ni][r] = 0.f;
    float l0 = 0.f, l1 = 0.f;

    const int ld_row = tid >> 1;
    const int ld_c0  = (tid & 1) * 32;
#define LOAD_KV(KB, STG) do {                                                  \
        const float* kg = k + (size_t)((KB) * 64 + ld_row) * DIM + h * HD + ld_c0; \
        const float* vg = v + (size_t)((KB) * 64 + ld_row) * DIM + h * HD + ld_c0; \
        float* kd = k_s + (STG) * 64 * AKSTR + ld_row * AKSTR + ld_c0;         \
        float* vd = v_s + (STG) * 64 * AVSTR + ld_row * AVSTR + ld_c0;         \
        _Pragma("unroll")                                                      \
        for (int i_ = 0; i_ < 8; i_++) {                                       \
            cp16(kd + i_ * 4, kg + i_ * 4);                                    \
            cp16(vd + i_ * 4, vg + i_ * 4);                                    \
        }                                                                      \
    } while (0)

    LOAD_KV(0, 0);
    asm volatile("cp.async.commit_group;\n");

    for (int kb = 0; kb <= qb; kb++) {
        if (kb < qb) {
            LOAD_KV(kb + 1, (kb + 1) & 1);
            asm volatile("cp.async.commit_group;\n");
            asm volatile("cp.async.wait_group 1;\n");
        } else {
            asm volatile("cp.async.wait_group 0;\n");
        }
        __syncthreads();

        const float* ks_ = k_s + (kb & 1) * 64 * AKSTR;
        const float* vs_ = v_s + (kb & 1) * 64 * AVSTR;

        float s[8][4];
#pragma unroll
        for (int ni = 0; ni < 8; ni++)
#pragma unroll
            for (int r = 0; r < 4; r++) s[ni][r] = 0.f;

#pragma unroll
        for (int ni = 0; ni < 8; ni++) {
            const float* kr = ks_ + (ni * 8 + gr) * AKSTR + tig;
#pragma unroll
            for (int ks = 0; ks < 8; ks++) {
                unsigned b[2];
                b[0] = f2tf32(kr[ks * 8]);
                b[1] = f2tf32(kr[ks * 8 + 4]);
                mma8(s[ni], aq[ks], b);
            }
        }

        const bool diag = (kb == qb);
        const int r0 = wrow + gr, r1 = r0 + 8;
#pragma unroll
        for (int ni = 0; ni < 8; ni++) {
            const int c0 = ni * 8 + 2 * tig;
            float p0 = __expf(s[ni][0] - 8.f);
            float p1 = __expf(s[ni][1] - 8.f);
            float p2 = __expf(s[ni][2] - 8.f);
            float p3 = __expf(s[ni][3] - 8.f);
            if (diag) {
                if (c0 > r0)     p0 = 0.f;
                if (c0 + 1 > r0) p1 = 0.f;
                if (c0 > r1)     p2 = 0.f;
                if (c0 + 1 > r1) p3 = 0.f;
            }
            l0 += p0 + p1;
            l1 += p2 + p3;
            uint2 w0; w0.x = f2tf32(p0); w0.y = f2tf32(p1);
            uint2 w1; w1.x = f2tf32(p2); w1.y = f2tf32(p3);
            *(uint2*)&p_s[r0 * AKSTR + c0] = w0;
            *(uint2*)&p_s[r1 * AKSTR + c0] = w1;
        }
        __syncwarp();

        const unsigned* pu = (const unsigned*)p_s;
#pragma unroll
        for (int ks = 0; ks < 8; ks++) {
            unsigned ap[4];
            ap[0] = pu[r0 * AKSTR + ks * 8 + tig];
            ap[1] = pu[r1 * AKSTR + ks * 8 + tig];
            ap[2] = pu[r0 * AKSTR + ks * 8 + 4 + tig];
            ap[3] = pu[r1 * AKSTR + ks * 8 + 4 + tig];
            const float* vr = vs_ + (ks * 8 + tig) * AVSTR + gr;
#pragma unroll
            for (int ni = 0; ni < 8; ni++) {
                unsigned b[2];
                b[0] = f2tf32(vr[ni * 8]);
                b[1] = f2tf32(vr[4 * AVSTR + ni * 8]);
                mma8(oacc[ni], ap, b);
            }
        }
        __syncthreads();
    }

    l0 += __shfl_xor_sync(0xffffffffu, l0, 1);
    l0 += __shfl_xor_sync(0xffffffffu, l0, 2);
    l1 += __shfl_xor_sync(0xffffffffu, l1, 1);
    l1 += __shfl_xor_sync(0xffffffffu, l1, 2);
    const float inv0 = 1.f / l0;
    const float inv1 = 1.f / l1;

    const int r0 = wrow + gr;
#pragma unroll
    for (int ni = 0; ni < 8; ni++) {
        const int c = ni * 8 + 2 * tig;
        float2 o0 = make_float2(oacc[ni][0] * inv0, oacc[ni][1] * inv0);
        float2 o1 = make_float2(oacc[ni][2] * inv1, oacc[ni][3] * inv1);
        *(float2*)&y[(size_t)(q0 + r0) * DIM + h * HD + c]     = o0;
        *(float2*)&y[(size_t)(q0 + r0 + 8) * DIM + h * HD + c] = o1;
    }
}

// ---------------- launch ----------------
extern "C" void kernel_launch(void* const* d_in, const int* in_sizes, int n_in,
                              void* d_out, int out_size)
{
    const float* x    = (const float*)d_in[0];
    const float* vi   = (const float*)d_in[1];
    const float* Wq   = (const float*)d_in[2];
    const float* Wk   = (const float*)d_in[3];
    const float* Wv   = (const float*)d_in[4];
    const float* Wp   = (const float*)d_in[5];
    const float* lamb = (const float*)d_in[6];
    float* out = (float*)d_out;

    float *q, *k, *v, *y;
    cudaGetSymbolAddress((void**)&q, g_q);
    cudaGetSymbolAddress((void**)&k, g_k);
    cudaGetSymbolAddress((void**)&v, g_v);
    cudaGetSymbolAddress((void**)&y, g_y);

    cudaFuncSetAttribute(gemm_tf32, cudaFuncAttributeMaxDynamicSharedMemorySize,
                         GEMM_SMEM_BYTES);
    cudaFuncSetAttribute(attn_tc_kernel, cudaFuncAttributeMaxDynamicSharedMemorySize,
                         ATTN_SMEM_BYTES);

    // fused QKV GEMM: z=0/1 -> Q/K with fused RMSNorm+RoPE, z=2 -> V blended
    dim3 gqkv(DIM / 128, T_LEN / 128, 3);
    gemm_tf32<<<gqkv, 256, GEMM_SMEM_BYTES>>>(x, Wq, Wk, Wv, q, k, v, vi, lamb,
                                              1, T_LEN, DIM, DIM);

    // tensor-core causal attention
    dim3 gattn(NH, T_LEN / 64);
    attn_tc_kernel<<<gattn, 128, ATTN_SMEM_BYTES>>>(q, k, v, y);

    // output projection
    dim3 gproj(DIM / 128, T_LEN / 128, 1);
    gemm_tf32<<<gproj, 256, GEMM_SMEM_BYTES>>>(y, Wp, Wp, Wp, out, out, out,
                                               nullptr, nullptr, 0, T_LEN, DIM, DIM);
}

// round 6
// speedup vs baseline: 1.6740x; 1.0403x over previous
#include <cuda_runtime.h>
#include <math.h>

#define T_LEN 2048
#define DIM   768
#define NH    12
#define HD    64

// ---------------- scratch (no allocation allowed) ----------------
__device__ float g_q[T_LEN * DIM];
__device__ float g_k[T_LEN * DIM];
__device__ float g_v[T_LEN * DIM];
__device__ float g_y[T_LEN * DIM];
__device__ float g_xr[T_LEN * DIM];
__device__ float g_wq[DIM * DIM];
__device__ float g_wk[DIM * DIM];
__device__ float g_wv[DIM * DIM];
__device__ float g_wp[DIM * DIM];

// ---------------- common tensor-core helpers ----------------
__device__ __forceinline__ unsigned f2tf32(float f) {
    unsigned u;
    asm("cvt.rna.tf32.f32 %0, %1;" : "=r"(u) : "f"(f));
    return u;
}

__device__ __forceinline__ float rnd_tf32(float f) {
    return __uint_as_float(f2tf32(f));
}

__device__ __forceinline__ void mma8(float* c, const unsigned* a, const unsigned* b) {
    asm volatile(
        "mma.sync.aligned.m16n8k8.row.col.f32.tf32.tf32.f32 "
        "{%0,%1,%2,%3}, {%4,%5,%6,%7}, {%8,%9}, {%0,%1,%2,%3};\n"
        : "+f"(c[0]), "+f"(c[1]), "+f"(c[2]), "+f"(c[3])
        : "r"(a[0]), "r"(a[1]), "r"(a[2]), "r"(a[3]), "r"(b[0]), "r"(b[1]));
}

__device__ __forceinline__ void cp16(void* smem_dst, const void* gsrc) {
    unsigned d = (unsigned)__cvta_generic_to_shared(smem_dst);
    asm volatile("cp.async.ca.shared.global [%0], [%1], 16;\n" :: "r"(d), "l"(gsrc));
}

// ---------------- tf32 pre-rounding pass ----------------
__global__ __launch_bounds__(256)
void tf32_round_kernel(const float* __restrict__ x,
                       const float* __restrict__ wq, const float* __restrict__ wk,
                       const float* __restrict__ wv, const float* __restrict__ wp,
                       float* __restrict__ xr,
                       float* __restrict__ wqr, float* __restrict__ wkr,
                       float* __restrict__ wvr, float* __restrict__ wpr)
{
    const int z = blockIdx.y;
    const float* s; float* d; int n;
    switch (z) {
        case 0: s = x;  d = xr;  n = T_LEN * DIM; break;
        case 1: s = wq; d = wqr; n = DIM * DIM;   break;
        case 2: s = wk; d = wkr; n = DIM * DIM;   break;
        case 3: s = wv; d = wvr; n = DIM * DIM;   break;
        default: s = wp; d = wpr; n = DIM * DIM;  break;
    }
    const int i = (blockIdx.x * 256 + threadIdx.x) * 4;
    if (i < n) {
        float4 v = *(const float4*)(s + i);
        v.x = rnd_tf32(v.x); v.y = rnd_tf32(v.y);
        v.z = rnd_tf32(v.z); v.w = rnd_tf32(v.w);
        *(float4*)(d + i) = v;
    }
}

// =====================================================================
// tf32 tensor-core GEMM:  C = A @ B^T   (A [M,K], B [N,K], C [M,N])
// CTA tile 128x128, 8 warps (2x4), warp tile 64x32. KC=32, 2-stage cp.async.
// Inputs MUST be tf32-pre-rounded; fragments are raw bit loads (no cvt).
// blockIdx.z selects (W,C); z==2 + addsrc: blended V output (rounded).
// do_normrope: z<2 -> fused per-head RMSNorm + RoPE epilogue (rounded store).
// =====================================================================
#define KC      32
#define GSTRIDE 36
#define STAGE_FLOATS (2 * 128 * GSTRIDE)
#define GEMM_SMEM_BYTES (2 * STAGE_FLOATS * 4)   // 73728

__device__ __forceinline__ void load_stage(float* As, float* Bs,
                                           const float* A, const float* B,
                                           int bm, int bn, int k0, int K, int tid)
{
    const int row = tid >> 3;
    const int col = (tid & 7) * 4;
#pragma unroll
    for (int p = 0; p < 4; p++) {
        const int r = row + p * 32;
        cp16(&As[r * GSTRIDE + col], A + (size_t)(bm + r) * K + k0 + col);
        cp16(&Bs[r * GSTRIDE + col], B + (size_t)(bn + r) * K + k0 + col);
    }
}

__global__ __launch_bounds__(256)
void gemm_tf32(const float* __restrict__ A,
               const float* __restrict__ W0, const float* __restrict__ W1,
               const float* __restrict__ W2,
               float* __restrict__ C0, float* __restrict__ C1, float* __restrict__ C2,
               const float* __restrict__ addsrc, const float* __restrict__ lamb_ptr,
               int do_normrope, int M, int N, int K)
{
    extern __shared__ float sm[];

    const int z = blockIdx.z;
    const float* B = (z == 0) ? W0 : (z == 1) ? W1 : W2;
    float*       C = (z == 0) ? C0 : (z == 1) ? C1 : C2;

    const int tid  = threadIdx.x;
    const int lane = tid & 31;
    const int warp = tid >> 5;
    const int wm   = warp >> 2;
    const int wn   = warp & 3;
    const int bm   = blockIdx.y * 128;
    const int bn   = blockIdx.x * 128;
    const int gr   = lane >> 2;
    const int tig  = lane & 3;

    float acc[4][4][4];
#pragma unroll
    for (int mi = 0; mi < 4; mi++)
#pragma unroll
        for (int ni = 0; ni < 4; ni++)
#pragma unroll
            for (int r = 0; r < 4; r++) acc[mi][ni][r] = 0.f;

    const int nt = K / KC;

    load_stage(sm, sm + 128 * GSTRIDE, A, B, bm, bn, 0, K, tid);
    asm volatile("cp.async.commit_group;\n");

    for (int t = 0; t < nt; t++) {
        if (t + 1 < nt) {
            float* dst = sm + ((t + 1) & 1) * STAGE_FLOATS;
            load_stage(dst, dst + 128 * GSTRIDE, A, B, bm, bn, (t + 1) * KC, K, tid);
            asm volatile("cp.async.commit_group;\n");
            asm volatile("cp.async.wait_group 1;\n");
        } else {
            asm volatile("cp.async.wait_group 0;\n");
        }
        __syncthreads();

        const unsigned* As = (const unsigned*)(sm + (t & 1) * STAGE_FLOATS);
        const unsigned* Bs = As + 128 * GSTRIDE;

#pragma unroll
        for (int ks = 0; ks < 4; ks++) {
            const int kk = ks * 8;
            unsigned a[4][4], b[4][2];
#pragma unroll
            for (int mi = 0; mi < 4; mi++) {
                const int r = wm * 64 + mi * 16 + gr;
                const int c = kk + tig;
                a[mi][0] = As[r * GSTRIDE + c];
                a[mi][1] = As[(r + 8) * GSTRIDE + c];
                a[mi][2] = As[r * GSTRIDE + c + 4];
                a[mi][3] = As[(r + 8) * GSTRIDE + c + 4];
            }
#pragma unroll
            for (int ni = 0; ni < 4; ni++) {
                const int n = wn * 32 + ni * 8 + gr;
                b[ni][0] = Bs[n * GSTRIDE + kk + tig];
                b[ni][1] = Bs[n * GSTRIDE + kk + 4 + tig];
            }
#pragma unroll
            for (int mi = 0; mi < 4; mi++)
#pragma unroll
                for (int ni = 0; ni < 4; ni++)
                    mma8(acc[mi][ni], a[mi], b[ni]);
        }
        __syncthreads();
    }

    if (do_normrope && z < 2) {
        // ---- stage acc tile into smem [128][132] ----
        float* st = sm;
#pragma unroll
        for (int mi = 0; mi < 4; mi++)
#pragma unroll
            for (int ni = 0; ni < 4; ni++) {
                const int r0 = wm * 64 + mi * 16 + gr;
                const int c0 = wn * 32 + ni * 8 + tig * 2;
                *(float2*)&st[r0 * 132 + c0]       = make_float2(acc[mi][ni][0], acc[mi][ni][1]);
                *(float2*)&st[(r0 + 8) * 132 + c0] = make_float2(acc[mi][ni][2], acc[mi][ni][3]);
            }
        __syncthreads();

        // ---- RMSNorm + RoPE; thread owns one (row, head); store rounded ----
        const int r  = tid >> 1;
        const int hh = tid & 1;
        const float* row = st + r * 132 + hh * 64;

        float x1[32], x2[32];
        float ss = 0.f;
#pragma unroll
        for (int i4 = 0; i4 < 8; i4++) {
            float4 u = *(const float4*)&row[i4 * 4];
            float4 w = *(const float4*)&row[i4 * 4 + 32];
            x1[i4 * 4 + 0] = u.x; x1[i4 * 4 + 1] = u.y; x1[i4 * 4 + 2] = u.z; x1[i4 * 4 + 3] = u.w;
            x2[i4 * 4 + 0] = w.x; x2[i4 * 4 + 1] = w.y; x2[i4 * 4 + 2] = w.z; x2[i4 * 4 + 3] = w.w;
            ss += u.x * u.x + u.y * u.y + u.z * u.z + u.w * u.w;
            ss += w.x * w.x + w.y * w.y + w.z * w.z + w.w * w.w;
        }
        const float rn = rsqrtf(ss * (1.f / 64.f) + 1.1920929e-07f);

        const int tok = bm + r;
        float o1[32], o2[32];
#pragma unroll
        for (int j = 0; j < 32; j++) {
            const float inv = expf(-(float)j * 0.28782313662425572f); // ln(1e4)/32
            const float ang = (float)tok * inv;
            const float c = cosf(ang);
            const float s = sinf(ang);
            const float a1 = x1[j] * rn, a2 = x2[j] * rn;
            o1[j] = rnd_tf32( a1 * c + a2 * s);
            o2[j] = rnd_tf32(-a1 * s + a2 * c);
        }
        float* Crow = C + (size_t)tok * N + bn + hh * 64;
#pragma unroll
        for (int i4 = 0; i4 < 8; i4++) {
            *(float4*)&Crow[i4 * 4]      = make_float4(o1[i4*4], o1[i4*4+1], o1[i4*4+2], o1[i4*4+3]);
            *(float4*)&Crow[i4 * 4 + 32] = make_float4(o2[i4*4], o2[i4*4+1], o2[i4*4+2], o2[i4*4+3]);
        }
        return;
    }

    // ---- plain / blended store ----
    const bool blend = (z == 2) && (addsrc != nullptr);
    const float lb = blend ? *lamb_ptr : 0.f;
    const float om = 1.f - lb;

#pragma unroll
    for (int mi = 0; mi < 4; mi++) {
#pragma unroll
        for (int ni = 0; ni < 4; ni++) {
            const int r0 = bm + wm * 64 + mi * 16 + gr;
            const int c0 = bn + wn * 32 + ni * 8 + tig * 2;
            float2 v0 = make_float2(acc[mi][ni][0], acc[mi][ni][1]);
            float2 v1 = make_float2(acc[mi][ni][2], acc[mi][ni][3]);
            if (blend) {
                const float* s0 = addsrc + (size_t)r0 * N + c0;
                const float* s1 = addsrc + (size_t)(r0 + 8) * N + c0;
                v0.x = rnd_tf32(om * v0.x + lb * s0[0]);
                v0.y = rnd_tf32(om * v0.y + lb * s0[1]);
                v1.x = rnd_tf32(om * v1.x + lb * s1[0]);
                v1.y = rnd_tf32(om * v1.y + lb * s1[1]);
            }
            *(float2*)(C + (size_t)r0 * N + c0)       = v0;
            *(float2*)(C + (size_t)(r0 + 8) * N + c0) = v1;
        }
    }
}

// =====================================================================
// tensor-core causal flash attention (tf32 MMA, fixed-shift softmax)
// q/k/v are tf32-pre-rounded -> fragment loads are raw bits (no cvt).
// =====================================================================
#define AKSTR 68
#define AVSTR 72
#define AT_K_OFF 0
#define AT_V_OFF (2 * 64 * AKSTR)
#define AT_P_OFF (AT_V_OFF + 2 * 64 * AVSTR)
#define ATTN_SMEM_FLOATS (AT_P_OFF + 64 * AKSTR)
#define ATTN_SMEM_BYTES  (ATTN_SMEM_FLOATS * 4)   // 89088

__global__ __launch_bounds__(128)
void attn_tc_kernel(const float* __restrict__ q, const float* __restrict__ k,
                    const float* __restrict__ v, float* __restrict__ y)
{
    extern __shared__ float sm[];
    float* k_s = sm + AT_K_OFF;
    float* v_s = sm + AT_V_OFF;
    float* p_s = sm + AT_P_OFF;

    const int h   = blockIdx.x;
    const int qb  = (gridDim.y - 1) - blockIdx.y;
    const int q0  = qb * 64;
    const int tid = threadIdx.x;
    const int w    = tid >> 5;
    const int lane = tid & 31;
    const int gr   = lane >> 2;
    const int tig  = lane & 3;
    const int wrow = w * 16;

    // q pre-rounded; *0.125f (exact pow2) keeps tf32-clean mantissa
    unsigned aq[8][4];
    {
        const float* qb_ = q + (size_t)(q0 + wrow) * DIM + h * HD;
#pragma unroll
        for (int ks = 0; ks < 8; ks++) {
            const int c = ks * 8 + tig;
            aq[ks][0] = __float_as_uint(0.125f * qb_[(size_t)gr * DIM + c]);
            aq[ks][1] = __float_as_uint(0.125f * qb_[(size_t)(gr + 8) * DIM + c]);
            aq[ks][2] = __float_as_uint(0.125f * qb_[(size_t)gr * DIM + c + 4]);
            aq[ks][3] = __float_as_uint(0.125f * qb_[(size_t)(gr + 8) * DIM + c + 4]);
        }
    }

    float oacc[8][4];
#pragma unroll
    for (int ni = 0; ni < 8; ni++)
#pragma unroll
        for (int r = 0; r < 4; r++) oacc[ni][r] = 0.f;
    float l0 = 0.f, l1 = 0.f;

    const int ld_row = tid >> 1;
    const int ld_c0  = (tid & 1) * 32;
#define LOAD_KV(KB, STG) do {                                                  \
        const float* kg = k + (size_t)((KB) * 64 + ld_row) * DIM + h * HD + ld_c0; \
        const float* vg = v + (size_t)((KB) * 64 + ld_row) * DIM + h * HD + ld_c0; \
        float* kd = k_s + (STG) * 64 * AKSTR + ld_row * AKSTR + ld_c0;         \
        float* vd = v_s + (STG) * 64 * AVSTR + ld_row * AVSTR + ld_c0;         \
        _Pragma("unroll")                                                      \
        for (int i_ = 0; i_ < 8; i_++) {                                       \
            cp16(kd + i_ * 4, kg + i_ * 4);                                    \
            cp16(vd + i_ * 4, vg + i_ * 4);                                    \
        }                                                                      \
    } while (0)

    LOAD_KV(0, 0);
    asm volatile("cp.async.commit_group;\n");

    for (int kb = 0; kb <= qb; kb++) {
        if (kb < qb) {
            LOAD_KV(kb + 1, (kb + 1) & 1);
            asm volatile("cp.async.commit_group;\n");
            asm volatile("cp.async.wait_group 1;\n");
        } else {
            asm volatile("cp.async.wait_group 0;\n");
        }
        __syncthreads();

        const unsigned* ks_ = (const unsigned*)(k_s + (kb & 1) * 64 * AKSTR);
        const unsigned* vs_ = (const unsigned*)(v_s + (kb & 1) * 64 * AVSTR);

        float s[8][4];
#pragma unroll
        for (int ni = 0; ni < 8; ni++)
#pragma unroll
            for (int r = 0; r < 4; r++) s[ni][r] = 0.f;

#pragma unroll
        for (int ni = 0; ni < 8; ni++) {
            const unsigned* kr = ks_ + (ni * 8 + gr) * AKSTR + tig;
#pragma unroll
            for (int ks = 0; ks < 8; ks++) {
                unsigned b[2];
                b[0] = kr[ks * 8];
                b[1] = kr[ks * 8 + 4];
                mma8(s[ni], aq[ks], b);
            }
        }

        const bool diag = (kb == qb);
        const int r0 = wrow + gr, r1 = r0 + 8;
#pragma unroll
        for (int ni = 0; ni < 8; ni++) {
            const int c0 = ni * 8 + 2 * tig;
            float p0 = __expf(s[ni][0] - 8.f);
            float p1 = __expf(s[ni][1] - 8.f);
            float p2 = __expf(s[ni][2] - 8.f);
            float p3 = __expf(s[ni][3] - 8.f);
            if (diag) {
                if (c0 > r0)     p0 = 0.f;
                if (c0 + 1 > r0) p1 = 0.f;
                if (c0 > r1)     p2 = 0.f;
                if (c0 + 1 > r1) p3 = 0.f;
            }
            l0 += p0 + p1;
            l1 += p2 + p3;
            uint2 w0; w0.x = f2tf32(p0); w0.y = f2tf32(p1);
            uint2 w1; w1.x = f2tf32(p2); w1.y = f2tf32(p3);
            *(uint2*)&p_s[r0 * AKSTR + c0] = w0;
            *(uint2*)&p_s[r1 * AKSTR + c0] = w1;
        }
        __syncwarp();

        const unsigned* pu = (const unsigned*)p_s;
#pragma unroll
        for (int ks = 0; ks < 8; ks++) {
            unsigned ap[4];
            ap[0] = pu[r0 * AKSTR + ks * 8 + tig];
            ap[1] = pu[r1 * AKSTR + ks * 8 + tig];
            ap[2] = pu[r0 * AKSTR + ks * 8 + 4 + tig];
            ap[3] = pu[r1 * AKSTR + ks * 8 + 4 + tig];
            const unsigned* vr = vs_ + (ks * 8 + tig) * AVSTR + gr;
#pragma unroll
            for (int ni = 0; ni < 8; ni++) {
                unsigned b[2];
                b[0] = vr[ni * 8];
                b[1] = vr[4 * AVSTR + ni * 8];
                mma8(oacc[ni], ap, b);
            }
        }
        __syncthreads();
    }

    l0 += __shfl_xor_sync(0xffffffffu, l0, 1);
    l0 += __shfl_xor_sync(0xffffffffu, l0, 2);
    l1 += __shfl_xor_sync(0xffffffffu, l1, 1);
    l1 += __shfl_xor_sync(0xffffffffu, l1, 2);
    const float inv0 = 1.f / l0;
    const float inv1 = 1.f / l1;

    // store y pre-rounded for the tf32 projection GEMM
    const int r0 = wrow + gr;
#pragma unroll
    for (int ni = 0; ni < 8; ni++) {
        const int c = ni * 8 + 2 * tig;
        float2 o0 = make_float2(rnd_tf32(oacc[ni][0] * inv0), rnd_tf32(oacc[ni][1] * inv0));
        float2 o1 = make_float2(rnd_tf32(oacc[ni][2] * inv1), rnd_tf32(oacc[ni][3] * inv1));
        *(float2*)&y[(size_t)(q0 + r0) * DIM + h * HD + c]     = o0;
        *(float2*)&y[(size_t)(q0 + r0 + 8) * DIM + h * HD + c] = o1;
    }
}

// ---------------- launch ----------------
extern "C" void kernel_launch(void* const* d_in, const int* in_sizes, int n_in,
                              void* d_out, int out_size)
{
    const float* x    = (const float*)d_in[0];
    const float* vi   = (const float*)d_in[1];
    const float* Wq   = (const float*)d_in[2];
    const float* Wk   = (const float*)d_in[3];
    const float* Wv   = (const float*)d_in[4];
    const float* Wp   = (const float*)d_in[5];
    const float* lamb = (const float*)d_in[6];
    float* out = (float*)d_out;

    float *q, *k, *v, *y, *xr, *wq, *wk, *wv, *wp;
    cudaGetSymbolAddress((void**)&q,  g_q);
    cudaGetSymbolAddress((void**)&k,  g_k);
    cudaGetSymbolAddress((void**)&v,  g_v);
    cudaGetSymbolAddress((void**)&y,  g_y);
    cudaGetSymbolAddress((void**)&xr, g_xr);
    cudaGetSymbolAddress((void**)&wq, g_wq);
    cudaGetSymbolAddress((void**)&wk, g_wk);
    cudaGetSymbolAddress((void**)&wv, g_wv);
    cudaGetSymbolAddress((void**)&wp, g_wp);

    cudaFuncSetAttribute(gemm_tf32, cudaFuncAttributeMaxDynamicSharedMemorySize,
                         GEMM_SMEM_BYTES);
    cudaFuncSetAttribute(attn_tc_kernel, cudaFuncAttributeMaxDynamicSharedMemorySize,
                         ATTN_SMEM_BYTES);

    // tf32 pre-rounding of x and all weights
    dim3 grnd((T_LEN * DIM / 4 + 255) / 256, 5);
    tf32_round_kernel<<<grnd, 256>>>(x, Wq, Wk, Wv, Wp, xr, wq, wk, wv, wp);

    // fused QKV GEMM: z=0/1 -> Q/K with fused RMSNorm+RoPE, z=2 -> V blended
    dim3 gqkv(DIM / 128, T_LEN / 128, 3);
    gemm_tf32<<<gqkv, 256, GEMM_SMEM_BYTES>>>(xr, wq, wk, wv, q, k, v, vi, lamb,
                                              1, T_LEN, DIM, DIM);

    // tensor-core causal attention
    dim3 gattn(NH, T_LEN / 64);
    attn_tc_kernel<<<gattn, 128, ATTN_SMEM_BYTES>>>(q, k, v, y);

    // output projection
    dim3 gproj(DIM / 128, T_LEN / 128, 1);
    gemm_tf32<<<gproj, 256, GEMM_SMEM_BYTES>>>(y, wp, wp, wp, out, out, out,
                                               nullptr, nullptr, 0, T_LEN, DIM, DIM);
}

// round 7
// speedup vs baseline: 2.3300x; 1.3918x over previous
#include <cuda_runtime.h>
#include <cuda_fp16.h>
#include <math.h>

#define T_LEN 2048
#define DIM   768
#define NH    12
#define HD    64

// ---------------- scratch (no allocation allowed) ----------------
__device__ __half g_xh[T_LEN * DIM];
__device__ __half g_wqh[DIM * DIM];
__device__ __half g_wkh[DIM * DIM];
__device__ __half g_wvh[DIM * DIM];
__device__ __half g_wph[DIM * DIM];
__device__ __half g_qh[T_LEN * DIM];
__device__ __half g_kh[T_LEN * DIM];
__device__ __half g_vth[DIM * T_LEN];   // V transposed: [dim][token]
__device__ __half g_yh[T_LEN * DIM];

// ---------------- helpers ----------------
__device__ __forceinline__ void mma16(float* c, const unsigned* a, const unsigned* b) {
    asm volatile(
        "mma.sync.aligned.m16n8k16.row.col.f32.f16.f16.f32 "
        "{%0,%1,%2,%3}, {%4,%5,%6,%7}, {%8,%9}, {%0,%1,%2,%3};\n"
        : "+f"(c[0]), "+f"(c[1]), "+f"(c[2]), "+f"(c[3])
        : "r"(a[0]), "r"(a[1]), "r"(a[2]), "r"(a[3]), "r"(b[0]), "r"(b[1]));
}

__device__ __forceinline__ void cp16(void* smem_dst, const void* gsrc) {
    unsigned d = (unsigned)__cvta_generic_to_shared(smem_dst);
    asm volatile("cp.async.ca.shared.global [%0], [%1], 16;\n" :: "r"(d), "l"(gsrc));
}

// ---------------- fp32 -> fp16 conversion pass ----------------
__global__ __launch_bounds__(256)
void cvt_half_kernel(const float* __restrict__ x,
                     const float* __restrict__ wq, const float* __restrict__ wk,
                     const float* __restrict__ wv, const float* __restrict__ wp,
                     __half* __restrict__ xh,
                     __half* __restrict__ wqh, __half* __restrict__ wkh,
                     __half* __restrict__ wvh, __half* __restrict__ wph)
{
    const int z = blockIdx.y;
    const float* s; __half* d; int n;
    switch (z) {
        case 0: s = x;  d = xh;  n = T_LEN * DIM; break;
        case 1: s = wq; d = wqh; n = DIM * DIM;   break;
        case 2: s = wk; d = wkh; n = DIM * DIM;   break;
        case 3: s = wv; d = wvh; n = DIM * DIM;   break;
        default: s = wp; d = wph; n = DIM * DIM;  break;
    }
    const int i = (blockIdx.x * 256 + threadIdx.x) * 4;
    if (i < n) {
        float4 v = *(const float4*)(s + i);
        *(__half2*)(d + i)     = __floats2half2_rn(v.x, v.y);
        *(__half2*)(d + i + 2) = __floats2half2_rn(v.z, v.w);
    }
}

// =====================================================================
// fp16 tensor-core GEMM:  C = A @ B^T   (A [M,K], B [N,K])
// CTA 128x128, 8 warps (2x4), warp tile 64x32. KC=32 halves, 2-stage
// cp.async, single sync per iteration.
// mode 0: plain fp32 store.  mode 1: z<2 RMSNorm+RoPE -> half C;
//                            z==2 blend with vi -> TRANSPOSED half C (vT).
// =====================================================================
#define KC    32
#define HSTR  40          // halves per smem row (20 words; 20 % 8 == 4)
#define HSTRW 20
#define STG_HALVES (2 * 128 * HSTR)
#define GEMM_SMEM_BYTES 69632      // >= max(2*STG_HALVES*2, 128*132*4)

__global__ __launch_bounds__(256, 2)
void gemm_f16(const __half* __restrict__ A,
              const __half* __restrict__ W0, const __half* __restrict__ W1,
              const __half* __restrict__ W2,
              void* C0v, void* C1v, void* C2v,
              const float* __restrict__ vi, const float* __restrict__ lamb_ptr,
              int mode, int M, int N, int K)
{
    extern __shared__ char smraw[];
    __half* smh = (__half*)smraw;

    const int z = blockIdx.z;
    const __half* B = (z == 0) ? W0 : (z == 1) ? W1 : W2;
    void* Cv = (z == 0) ? C0v : (z == 1) ? C1v : C2v;

    const int tid  = threadIdx.x;
    const int lane = tid & 31;
    const int warp = tid >> 5;
    const int wm   = warp >> 2;
    const int wn   = warp & 3;
    const int bm   = blockIdx.y * 128;
    const int bn   = blockIdx.x * 128;
    const int gr   = lane >> 2;
    const int tig  = lane & 3;

    const int lmat = tid >> 7;
    const int lrow = tid & 127;
    const __half* lsrc = lmat ? B + (size_t)(bn + lrow) * K
                              : A + (size_t)(bm + lrow) * K;

    float acc[4][4][4];
#pragma unroll
    for (int mi = 0; mi < 4; mi++)
#pragma unroll
        for (int ni = 0; ni < 4; ni++)
#pragma unroll
            for (int r = 0; r < 4; r++) acc[mi][ni][r] = 0.f;

    const int nt = K / KC;

#define GLOAD(T, STG) do {                                                   \
        __half* dst_ = smh + (STG) * STG_HALVES + lmat * 128 * HSTR + lrow * HSTR; \
        const __half* s_ = lsrc + (T) * KC;                                  \
        cp16(dst_, s_); cp16(dst_ + 8, s_ + 8);                              \
        cp16(dst_ + 16, s_ + 16); cp16(dst_ + 24, s_ + 24);                  \
    } while (0)

    GLOAD(0, 0);
    asm volatile("cp.async.commit_group;\n");

    for (int t = 0; t < nt; t++) {
        asm volatile("cp.async.wait_group 0;\n");
        __syncthreads();
        if (t + 1 < nt) {
            GLOAD(t + 1, (t + 1) & 1);
            asm volatile("cp.async.commit_group;\n");
        }

        const unsigned* As = (const unsigned*)(smh + (t & 1) * STG_HALVES);
        const unsigned* Bs = As + 128 * HSTRW;

#pragma unroll
        for (int ks2 = 0; ks2 < 2; ks2++) {
            unsigned a[4][4], b[4][2];
#pragma unroll
            for (int mi = 0; mi < 4; mi++) {
                const int r = wm * 64 + mi * 16 + gr;
                a[mi][0] = As[r * HSTRW + ks2 * 8 + tig];
                a[mi][1] = As[(r + 8) * HSTRW + ks2 * 8 + tig];
                a[mi][2] = As[r * HSTRW + ks2 * 8 + 4 + tig];
                a[mi][3] = As[(r + 8) * HSTRW + ks2 * 8 + 4 + tig];
            }
#pragma unroll
            for (int ni = 0; ni < 4; ni++) {
                const int n = wn * 32 + ni * 8 + gr;
                b[ni][0] = Bs[n * HSTRW + ks2 * 8 + tig];
                b[ni][1] = Bs[n * HSTRW + ks2 * 8 + 4 + tig];
            }
#pragma unroll
            for (int mi = 0; mi < 4; mi++)
#pragma unroll
                for (int ni = 0; ni < 4; ni++)
                    mma16(acc[mi][ni], a[mi], b[ni]);
        }
    }

    if (mode == 1 && z < 2) {
        // ---- RMSNorm + RoPE epilogue; half output ----
        __syncthreads();
        float* st = (float*)smraw;            // [128][132]
#pragma unroll
        for (int mi = 0; mi < 4; mi++)
#pragma unroll
            for (int ni = 0; ni < 4; ni++) {
                const int r0 = wm * 64 + mi * 16 + gr;
                const int c0 = wn * 32 + ni * 8 + tig * 2;
                *(float2*)&st[r0 * 132 + c0]       = make_float2(acc[mi][ni][0], acc[mi][ni][1]);
                *(float2*)&st[(r0 + 8) * 132 + c0] = make_float2(acc[mi][ni][2], acc[mi][ni][3]);
            }
        __syncthreads();

        const int r  = tid >> 1;
        const int hh = tid & 1;
        const float* row = st + r * 132 + hh * 64;

        float x1[32], x2[32];
        float ss = 0.f;
#pragma unroll
        for (int i4 = 0; i4 < 8; i4++) {
            float4 u = *(const float4*)&row[i4 * 4];
            float4 w = *(const float4*)&row[i4 * 4 + 32];
            x1[i4 * 4 + 0] = u.x; x1[i4 * 4 + 1] = u.y; x1[i4 * 4 + 2] = u.z; x1[i4 * 4 + 3] = u.w;
            x2[i4 * 4 + 0] = w.x; x2[i4 * 4 + 1] = w.y; x2[i4 * 4 + 2] = w.z; x2[i4 * 4 + 3] = w.w;
            ss += u.x * u.x + u.y * u.y + u.z * u.z + u.w * u.w;
            ss += w.x * w.x + w.y * w.y + w.z * w.z + w.w * w.w;
        }
        const float rn = rsqrtf(ss * (1.f / 64.f) + 1.1920929e-07f);

        const int tok = bm + r;
        __half* Crow = (__half*)Cv + (size_t)tok * N + bn + hh * 64;
#pragma unroll
        for (int j2 = 0; j2 < 16; j2++) {
            float o1a, o1b, o2a, o2b;
#pragma unroll
            for (int e = 0; e < 2; e++) {
                const int j = j2 * 2 + e;
                const float inv = expf(-(float)j * 0.28782313662425572f); // ln(1e4)/32
                const float ang = (float)tok * inv;
                const float c = cosf(ang);
                const float s = sinf(ang);
                const float a1 = x1[j] * rn, a2 = x2[j] * rn;
                const float o1 =  a1 * c + a2 * s;
                const float o2 = -a1 * s + a2 * c;
                if (e == 0) { o1a = o1; o2a = o2; } else { o1b = o1; o2b = o2; }
            }
            *(__half2*)&Crow[j2 * 2]      = __floats2half2_rn(o1a, o1b);
            *(__half2*)&Crow[32 + j2 * 2] = __floats2half2_rn(o2a, o2b);
        }
        return;
    }

    if (mode == 1) {
        // ---- V: blend with vi, store TRANSPOSED half ([dim][token]) ----
        __syncthreads();
        __half* sh = (__half*)smraw;          // [128][136]
        const float lb = *lamb_ptr;
        const float om = 1.f - lb;
#pragma unroll
        for (int mi = 0; mi < 4; mi++)
#pragma unroll
            for (int ni = 0; ni < 4; ni++) {
                const int r0 = wm * 64 + mi * 16 + gr;
                const int c0 = wn * 32 + ni * 8 + tig * 2;
                const float* s0 = vi + (size_t)(bm + r0) * N + bn + c0;
                const float* s1 = vi + (size_t)(bm + r0 + 8) * N + bn + c0;
                *(__half2*)&sh[r0 * 136 + c0] = __floats2half2_rn(
                    om * acc[mi][ni][0] + lb * s0[0], om * acc[mi][ni][1] + lb * s0[1]);
                *(__half2*)&sh[(r0 + 8) * 136 + c0] = __floats2half2_rn(
                    om * acc[mi][ni][2] + lb * s1[0], om * acc[mi][ni][3] + lb * s1[1]);
            }
        __syncthreads();

        const int cl = tid >> 1;      // dim within tile 0..127
        const int th = tid & 1;       // token half
        __half* dst = (__half*)Cv + (size_t)(bn + cl) * T_LEN + bm + th * 64;
#pragma unroll
        for (int j = 0; j < 32; j++) {
            __half a0 = sh[(th * 64 + 2 * j) * 136 + cl];
            __half a1 = sh[(th * 64 + 2 * j + 1) * 136 + cl];
            *(__half2*)&dst[2 * j] = __halves2half2(a0, a1);
        }
        return;
    }

    // ---- mode 0: plain fp32 store ----
    float* C = (float*)Cv;
#pragma unroll
    for (int mi = 0; mi < 4; mi++) {
#pragma unroll
        for (int ni = 0; ni < 4; ni++) {
            const int r0 = bm + wm * 64 + mi * 16 + gr;
            const int c0 = bn + wn * 32 + ni * 8 + tig * 2;
            *(float2*)(C + (size_t)r0 * N + c0)       = make_float2(acc[mi][ni][0], acc[mi][ni][1]);
            *(float2*)(C + (size_t)(r0 + 8) * N + c0) = make_float2(acc[mi][ni][2], acc[mi][ni][3]);
        }
    }
}

// =====================================================================
// fp16 tensor-core causal flash attention (fixed-shift softmax)
// CTA = (64-query block, head); 4 warps; 4 CTAs/SM.
// =====================================================================
#define ASTRH 72     // halves per row (36 words; 36 % 8 == 4: conflict-free)
#define ASTRW 36
#define AT_K 0
#define AT_V (2 * 64 * ASTRH)
#define AT_P (AT_V + 2 * 64 * ASTRH)
#define ATTN_SMEM_BYTES ((AT_P + 64 * ASTRH) * 2)   // 46080

__global__ __launch_bounds__(128, 4)
void attn_f16(const __half* __restrict__ q, const __half* __restrict__ k,
              const __half* __restrict__ vt, __half* __restrict__ y)
{
    extern __shared__ char smraw[];
    __half* smh = (__half*)smraw;
    __half* k_s = smh + AT_K;
    __half* v_s = smh + AT_V;
    __half* p_s = smh + AT_P;

    const int h   = blockIdx.x;
    const int qb  = (gridDim.y - 1) - blockIdx.y;     // longest-first
    const int q0  = qb * 64;
    const int tid = threadIdx.x;
    const int w    = tid >> 5;
    const int lane = tid & 31;
    const int gr   = lane >> 2;
    const int tig  = lane & 3;
    const int wrow = w * 16;

    // Q fragments (raw fp16 bits; scale applied post-MMA)
    unsigned aq[4][4];
    {
        const __half* qb_ = q + (size_t)(q0 + wrow) * DIM + h * HD;
#pragma unroll
        for (int ks2 = 0; ks2 < 4; ks2++) {
            aq[ks2][0] = *(const unsigned*)&qb_[(size_t)gr * DIM + ks2 * 16 + 2 * tig];
            aq[ks2][1] = *(const unsigned*)&qb_[(size_t)(gr + 8) * DIM + ks2 * 16 + 2 * tig];
            aq[ks2][2] = *(const unsigned*)&qb_[(size_t)gr * DIM + ks2 * 16 + 8 + 2 * tig];
            aq[ks2][3] = *(const unsigned*)&qb_[(size_t)(gr + 8) * DIM + ks2 * 16 + 8 + 2 * tig];
        }
    }

    float oacc[8][4];
#pragma unroll
    for (int ni = 0; ni < 8; ni++)
#pragma unroll
        for (int r = 0; r < 4; r++) oacc[ni][r] = 0.f;
    float l0 = 0.f, l1 = 0.f;

    const int ar = tid >> 1;
    const int ac = (tid & 1) * 32;
#define LOAD_KV(KB, STG) do {                                                  \
        const __half* kg = k + (size_t)((KB) * 64 + ar) * DIM + h * HD + ac;   \
        const __half* vg = vt + (size_t)(h * HD + ar) * T_LEN + (KB) * 64 + ac;\
        __half* kd = k_s + (STG) * 64 * ASTRH + ar * ASTRH + ac;               \
        __half* vd = v_s + (STG) * 64 * ASTRH + ar * ASTRH + ac;               \
        cp16(kd, kg); cp16(kd + 8, kg + 8); cp16(kd + 16, kg + 16); cp16(kd + 24, kg + 24); \
        cp16(vd, vg); cp16(vd + 8, vg + 8); cp16(vd + 16, vg + 16); cp16(vd + 24, vg + 24); \
    } while (0)

    LOAD_KV(0, 0);
    asm volatile("cp.async.commit_group;\n");

    for (int kb = 0; kb <= qb; kb++) {
        asm volatile("cp.async.wait_group 0;\n");
        __syncthreads();
        if (kb < qb) {
            LOAD_KV(kb + 1, (kb + 1) & 1);
            asm volatile("cp.async.commit_group;\n");
        }

        const unsigned* Kw = (const unsigned*)(k_s + (kb & 1) * 64 * ASTRH);
        const unsigned* Vw = (const unsigned*)(v_s + (kb & 1) * 64 * ASTRH);

        // ---- S = Q K^T (raw) ----
        float s[8][4];
#pragma unroll
        for (int ni = 0; ni < 8; ni++)
#pragma unroll
            for (int r = 0; r < 4; r++) s[ni][r] = 0.f;

#pragma unroll
        for (int ni = 0; ni < 8; ni++) {
            const unsigned* kr = Kw + (ni * 8 + gr) * ASTRW + tig;
#pragma unroll
            for (int ks2 = 0; ks2 < 4; ks2++) {
                unsigned b[2];
                b[0] = kr[ks2 * 8];
                b[1] = kr[ks2 * 8 + 4];
                mma16(s[ni], aq[ks2], b);
            }
        }

        // ---- fixed-shift softmax (scale 0.125 post-MMA), P as fp16 ----
        const bool diag = (kb == qb);
        const int r0 = wrow + gr, r1 = r0 + 8;
#pragma unroll
        for (int ni = 0; ni < 8; ni++) {
            const int c0 = ni * 8 + 2 * tig;
            float p0 = __expf(fmaf(s[ni][0], 0.125f, -8.f));
            float p1 = __expf(fmaf(s[ni][1], 0.125f, -8.f));
            float p2 = __expf(fmaf(s[ni][2], 0.125f, -8.f));
            float p3 = __expf(fmaf(s[ni][3], 0.125f, -8.f));
            if (diag) {
                if (c0 > r0)     p0 = 0.f;
                if (c0 + 1 > r0) p1 = 0.f;
                if (c0 > r1)     p2 = 0.f;
                if (c0 + 1 > r1) p3 = 0.f;
            }
            l0 += p0 + p1;
            l1 += p2 + p3;
            *(__half2*)&p_s[r0 * ASTRH + c0] = __floats2half2_rn(p0, p1);
            *(__half2*)&p_s[r1 * ASTRH + c0] = __floats2half2_rn(p2, p3);
        }
        __syncwarp();

        // ---- O += P V  (B = V^T tile: [dim][key]) ----
        const unsigned* Pw = (const unsigned*)p_s;
#pragma unroll
        for (int ks2 = 0; ks2 < 4; ks2++) {
            unsigned ap[4];
            ap[0] = Pw[r0 * ASTRW + ks2 * 8 + tig];
            ap[1] = Pw[r1 * ASTRW + ks2 * 8 + tig];
            ap[2] = Pw[r0 * ASTRW + ks2 * 8 + 4 + tig];
            ap[3] = Pw[r1 * ASTRW + ks2 * 8 + 4 + tig];
#pragma unroll
            for (int ni = 0; ni < 8; ni++) {
                const unsigned* vr = Vw + (ni * 8 + gr) * ASTRW + tig;
                unsigned b[2];
                b[0] = vr[ks2 * 8];
                b[1] = vr[ks2 * 8 + 4];
                mma16(oacc[ni], ap, b);
            }
        }
    }

    l0 += __shfl_xor_sync(0xffffffffu, l0, 1);
    l0 += __shfl_xor_sync(0xffffffffu, l0, 2);
    l1 += __shfl_xor_sync(0xffffffffu, l1, 1);
    l1 += __shfl_xor_sync(0xffffffffu, l1, 2);
    const float inv0 = 1.f / l0;
    const float inv1 = 1.f / l1;

    const int r0 = wrow + gr;
#pragma unroll
    for (int ni = 0; ni < 8; ni++) {
        const int c = ni * 8 + 2 * tig;
        *(__half2*)&y[(size_t)(q0 + r0) * DIM + h * HD + c] =
            __floats2half2_rn(oacc[ni][0] * inv0, oacc[ni][1] * inv0);
        *(__half2*)&y[(size_t)(q0 + r0 + 8) * DIM + h * HD + c] =
            __floats2half2_rn(oacc[ni][2] * inv1, oacc[ni][3] * inv1);
    }
}

// ---------------- launch ----------------
extern "C" void kernel_launch(void* const* d_in, const int* in_sizes, int n_in,
                              void* d_out, int out_size)
{
    const float* x    = (const float*)d_in[0];
    const float* vi   = (const float*)d_in[1];
    const float* Wq   = (const float*)d_in[2];
    const float* Wk   = (const float*)d_in[3];
    const float* Wv   = (const float*)d_in[4];
    const float* Wp   = (const float*)d_in[5];
    const float* lamb = (const float*)d_in[6];
    float* out = (float*)d_out;

    __half *xh, *wqh, *wkh, *wvh, *wph, *qh, *kh, *vth, *yh;
    cudaGetSymbolAddress((void**)&xh,  g_xh);
    cudaGetSymbolAddress((void**)&wqh, g_wqh);
    cudaGetSymbolAddress((void**)&wkh, g_wkh);
    cudaGetSymbolAddress((void**)&wvh, g_wvh);
    cudaGetSymbolAddress((void**)&wph, g_wph);
    cudaGetSymbolAddress((void**)&qh,  g_qh);
    cudaGetSymbolAddress((void**)&kh,  g_kh);
    cudaGetSymbolAddress((void**)&vth, g_vth);
    cudaGetSymbolAddress((void**)&yh,  g_yh);

    cudaFuncSetAttribute(gemm_f16, cudaFuncAttributeMaxDynamicSharedMemorySize,
                         GEMM_SMEM_BYTES);
    cudaFuncSetAttribute(attn_f16, cudaFuncAttributeMaxDynamicSharedMemorySize,
                         ATTN_SMEM_BYTES);

    // fp32 -> fp16 conversion of x and all weights
    dim3 gcvt((T_LEN * DIM / 4 + 255) / 256, 5);
    cvt_half_kernel<<<gcvt, 256>>>(x, Wq, Wk, Wv, Wp, xh, wqh, wkh, wvh, wph);

    // fused QKV: z=0/1 -> q/k (norm+rope, half), z=2 -> blended V transposed
    dim3 gqkv(DIM / 128, T_LEN / 128, 3);
    gemm_f16<<<gqkv, 256, GEMM_SMEM_BYTES>>>(xh, wqh, wkh, wvh, qh, kh, vth,
                                             vi, lamb, 1, T_LEN, DIM, DIM);

    // fp16 tensor-core causal attention
    dim3 gattn(NH, T_LEN / 64);
    attn_f16<<<gattn, 128, ATTN_SMEM_BYTES>>>(qh, kh, vth, yh);

    // output projection (fp32 out)
    dim3 gproj(DIM / 128, T_LEN / 128, 1);
    gemm_f16<<<gproj, 256, GEMM_SMEM_BYTES>>>(yh, wph, wph, wph, out, out, out,
                                              nullptr, nullptr, 0, T_LEN, DIM, DIM);
}

// round 8
// speedup vs baseline: 2.3314x; 1.0006x over previous
#include <cuda_runtime.h>
#include <cuda_fp16.h>
#include <math.h>

#define T_LEN 2048
#define DIM   768
#define NH    12
#define HD    64

// ---------------- scratch (no allocation allowed) ----------------
__device__ __half g_xh[T_LEN * DIM];
__device__ __half g_wqh[DIM * DIM];
__device__ __half g_wkh[DIM * DIM];
__device__ __half g_wvh[DIM * DIM];
__device__ __half g_wph[DIM * DIM];
__device__ __half g_qh[T_LEN * DIM];
__device__ __half g_kh[T_LEN * DIM];
__device__ __half g_vth[DIM * T_LEN];   // V transposed: [dim][token]
__device__ __half g_yh[T_LEN * DIM];

// ---------------- helpers ----------------
__device__ __forceinline__ void mma16(float* c, const unsigned* a, const unsigned* b) {
    asm volatile(
        "mma.sync.aligned.m16n8k16.row.col.f32.f16.f16.f32 "
        "{%0,%1,%2,%3}, {%4,%5,%6,%7}, {%8,%9}, {%0,%1,%2,%3};\n"
        : "+f"(c[0]), "+f"(c[1]), "+f"(c[2]), "+f"(c[3])
        : "r"(a[0]), "r"(a[1]), "r"(a[2]), "r"(a[3]), "r"(b[0]), "r"(b[1]));
}

__device__ __forceinline__ void cp16(void* smem_dst, const void* gsrc) {
    unsigned d = (unsigned)__cvta_generic_to_shared(smem_dst);
    asm volatile("cp.async.ca.shared.global [%0], [%1], 16;\n" :: "r"(d), "l"(gsrc));
}

// ---------------- fp32 -> fp16 conversion pass ----------------
__global__ __launch_bounds__(256)
void cvt_half_kernel(const float* __restrict__ x,
                     const float* __restrict__ wq, const float* __restrict__ wk,
                     const float* __restrict__ wv, const float* __restrict__ wp,
                     __half* __restrict__ xh,
                     __half* __restrict__ wqh, __half* __restrict__ wkh,
                     __half* __restrict__ wvh, __half* __restrict__ wph)
{
    const int z = blockIdx.y;
    const float* s; __half* d; int n;
    switch (z) {
        case 0: s = x;  d = xh;  n = T_LEN * DIM; break;
        case 1: s = wq; d = wqh; n = DIM * DIM;   break;
        case 2: s = wk; d = wkh; n = DIM * DIM;   break;
        case 3: s = wv; d = wvh; n = DIM * DIM;   break;
        default: s = wp; d = wph; n = DIM * DIM;  break;
    }
    const int i = (blockIdx.x * 256 + threadIdx.x) * 4;
    if (i < n) {
        float4 v = *(const float4*)(s + i);
        *(__half2*)(d + i)     = __floats2half2_rn(v.x, v.y);
        *(__half2*)(d + i + 2) = __floats2half2_rn(v.z, v.w);
    }
}

// =====================================================================
// fp16 tensor-core GEMM:  C = A @ B^T   (A [M,K], B [N,K])
// CTA 128x128, 8 warps (2x4), warp tile 64x32. KC=32 halves, 2-stage
// cp.async with prefetch-then-wait_group(1) pipelining.
// mode 0: plain fp32 store.  mode 1: z<2 RMSNorm+RoPE -> half C;
//                            z==2 blend with vi -> TRANSPOSED half C (vT).
// =====================================================================
#define KC    32
#define HSTR  40          // halves per smem row (20 words; 20 % 8 == 4)
#define HSTRW 20
#define STG_HALVES (2 * 128 * HSTR)
#define GEMM_SMEM_BYTES 69632      // >= max(2*STG_HALVES*2, 128*132*4)

__global__ __launch_bounds__(256, 2)
void gemm_f16(const __half* __restrict__ A,
              const __half* __restrict__ W0, const __half* __restrict__ W1,
              const __half* __restrict__ W2,
              void* C0v, void* C1v, void* C2v,
              const float* __restrict__ vi, const float* __restrict__ lamb_ptr,
              int mode, int M, int N, int K)
{
    extern __shared__ char smraw[];
    __half* smh = (__half*)smraw;

    const int z = blockIdx.z;
    const __half* B = (z == 0) ? W0 : (z == 1) ? W1 : W2;
    void* Cv = (z == 0) ? C0v : (z == 1) ? C1v : C2v;

    const int tid  = threadIdx.x;
    const int lane = tid & 31;
    const int warp = tid >> 5;
    const int wm   = warp >> 2;
    const int wn   = warp & 3;
    const int bm   = blockIdx.y * 128;
    const int bn   = blockIdx.x * 128;
    const int gr   = lane >> 2;
    const int tig  = lane & 3;

    const int lmat = tid >> 7;
    const int lrow = tid & 127;
    const __half* lsrc = lmat ? B + (size_t)(bn + lrow) * K
                              : A + (size_t)(bm + lrow) * K;

    float acc[4][4][4];
#pragma unroll
    for (int mi = 0; mi < 4; mi++)
#pragma unroll
        for (int ni = 0; ni < 4; ni++)
#pragma unroll
            for (int r = 0; r < 4; r++) acc[mi][ni][r] = 0.f;

    const int nt = K / KC;

#define GLOAD(T, STG) do {                                                   \
        __half* dst_ = smh + (STG) * STG_HALVES + lmat * 128 * HSTR + lrow * HSTR; \
        const __half* s_ = lsrc + (T) * KC;                                  \
        cp16(dst_, s_); cp16(dst_ + 8, s_ + 8);                              \
        cp16(dst_ + 16, s_ + 16); cp16(dst_ + 24, s_ + 24);                  \
    } while (0)

    GLOAD(0, 0);
    asm volatile("cp.async.commit_group;\n");

    for (int t = 0; t < nt; t++) {
        if (t + 1 < nt) {
            GLOAD(t + 1, (t + 1) & 1);
            asm volatile("cp.async.commit_group;\n");
            asm volatile("cp.async.wait_group 1;\n");
        } else {
            asm volatile("cp.async.wait_group 0;\n");
        }
        __syncthreads();

        const unsigned* As = (const unsigned*)(smh + (t & 1) * STG_HALVES);
        const unsigned* Bs = As + 128 * HSTRW;

#pragma unroll
        for (int ks2 = 0; ks2 < 2; ks2++) {
            unsigned a[4][4], b[4][2];
#pragma unroll
            for (int mi = 0; mi < 4; mi++) {
                const int r = wm * 64 + mi * 16 + gr;
                a[mi][0] = As[r * HSTRW + ks2 * 8 + tig];
                a[mi][1] = As[(r + 8) * HSTRW + ks2 * 8 + tig];
                a[mi][2] = As[r * HSTRW + ks2 * 8 + 4 + tig];
                a[mi][3] = As[(r + 8) * HSTRW + ks2 * 8 + 4 + tig];
            }
#pragma unroll
            for (int ni = 0; ni < 4; ni++) {
                const int n = wn * 32 + ni * 8 + gr;
                b[ni][0] = Bs[n * HSTRW + ks2 * 8 + tig];
                b[ni][1] = Bs[n * HSTRW + ks2 * 8 + 4 + tig];
            }
#pragma unroll
            for (int mi = 0; mi < 4; mi++)
#pragma unroll
                for (int ni = 0; ni < 4; ni++)
                    mma16(acc[mi][ni], a[mi], b[ni]);
        }
        __syncthreads();
    }

    if (mode == 1 && z < 2) {
        // ---- RMSNorm + RoPE epilogue; half output ----
        float* st = (float*)smraw;            // [128][132]
#pragma unroll
        for (int mi = 0; mi < 4; mi++)
#pragma unroll
            for (int ni = 0; ni < 4; ni++) {
                const int r0 = wm * 64 + mi * 16 + gr;
                const int c0 = wn * 32 + ni * 8 + tig * 2;
                *(float2*)&st[r0 * 132 + c0]       = make_float2(acc[mi][ni][0], acc[mi][ni][1]);
                *(float2*)&st[(r0 + 8) * 132 + c0] = make_float2(acc[mi][ni][2], acc[mi][ni][3]);
            }
        __syncthreads();

        const int r  = tid >> 1;
        const int hh = tid & 1;
        const float* row = st + r * 132 + hh * 64;

        float x1[32], x2[32];
        float ss = 0.f;
#pragma unroll
        for (int i4 = 0; i4 < 8; i4++) {
            float4 u = *(const float4*)&row[i4 * 4];
            float4 w = *(const float4*)&row[i4 * 4 + 32];
            x1[i4 * 4 + 0] = u.x; x1[i4 * 4 + 1] = u.y; x1[i4 * 4 + 2] = u.z; x1[i4 * 4 + 3] = u.w;
            x2[i4 * 4 + 0] = w.x; x2[i4 * 4 + 1] = w.y; x2[i4 * 4 + 2] = w.z; x2[i4 * 4 + 3] = w.w;
            ss += u.x * u.x + u.y * u.y + u.z * u.z + u.w * u.w;
            ss += w.x * w.x + w.y * w.y + w.z * w.z + w.w * w.w;
        }
        const float rn = rsqrtf(ss * (1.f / 64.f) + 1.1920929e-07f);

        const int tok = bm + r;
        __half* Crow = (__half*)Cv + (size_t)tok * N + bn + hh * 64;
#pragma unroll
        for (int j2 = 0; j2 < 16; j2++) {
            float o1a, o1b, o2a, o2b;
#pragma unroll
            for (int e = 0; e < 2; e++) {
                const int j = j2 * 2 + e;
                const float inv = expf(-(float)j * 0.28782313662425572f); // ln(1e4)/32
                const float ang = (float)tok * inv;
                const float c = cosf(ang);
                const float s = sinf(ang);
                const float a1 = x1[j] * rn, a2 = x2[j] * rn;
                const float o1 =  a1 * c + a2 * s;
                const float o2 = -a1 * s + a2 * c;
                if (e == 0) { o1a = o1; o2a = o2; } else { o1b = o1; o2b = o2; }
            }
            *(__half2*)&Crow[j2 * 2]      = __floats2half2_rn(o1a, o1b);
            *(__half2*)&Crow[32 + j2 * 2] = __floats2half2_rn(o2a, o2b);
        }
        return;
    }

    if (mode == 1) {
        // ---- V: blend with vi, store TRANSPOSED half ([dim][token]) ----
        __half* sh = (__half*)smraw;          // [128][136]
        const float lb = *lamb_ptr;
        const float om = 1.f - lb;
#pragma unroll
        for (int mi = 0; mi < 4; mi++)
#pragma unroll
            for (int ni = 0; ni < 4; ni++) {
                const int r0 = wm * 64 + mi * 16 + gr;
                const int c0 = wn * 32 + ni * 8 + tig * 2;
                const float* s0 = vi + (size_t)(bm + r0) * N + bn + c0;
                const float* s1 = vi + (size_t)(bm + r0 + 8) * N + bn + c0;
                *(__half2*)&sh[r0 * 136 + c0] = __floats2half2_rn(
                    om * acc[mi][ni][0] + lb * s0[0], om * acc[mi][ni][1] + lb * s0[1]);
                *(__half2*)&sh[(r0 + 8) * 136 + c0] = __floats2half2_rn(
                    om * acc[mi][ni][2] + lb * s1[0], om * acc[mi][ni][3] + lb * s1[1]);
            }
        __syncthreads();

        const int cl = tid >> 1;      // dim within tile 0..127
        const int th = tid & 1;       // token half
        __half* dst = (__half*)Cv + (size_t)(bn + cl) * T_LEN + bm + th * 64;
#pragma unroll
        for (int j = 0; j < 32; j++) {
            __half a0 = sh[(th * 64 + 2 * j) * 136 + cl];
            __half a1 = sh[(th * 64 + 2 * j + 1) * 136 + cl];
            *(__half2*)&dst[2 * j] = __halves2half2(a0, a1);
        }
        return;
    }

    // ---- mode 0: plain fp32 store ----
    float* C = (float*)Cv;
#pragma unroll
    for (int mi = 0; mi < 4; mi++) {
#pragma unroll
        for (int ni = 0; ni < 4; ni++) {
            const int r0 = bm + wm * 64 + mi * 16 + gr;
            const int c0 = bn + wn * 32 + ni * 8 + tig * 2;
            *(float2*)(C + (size_t)r0 * N + c0)       = make_float2(acc[mi][ni][0], acc[mi][ni][1]);
            *(float2*)(C + (size_t)(r0 + 8) * N + c0) = make_float2(acc[mi][ni][2], acc[mi][ni][3]);
        }
    }
}

// =====================================================================
// fp16 tensor-core causal flash attention (fixed-shift softmax)
// CTA = (64-query block, head); 4 warps; 4 CTAs/SM.
// =====================================================================
#define ASTRH 72     // halves per row (36 words; 36 % 8 == 4: conflict-free)
#define ASTRW 36
#define AT_K 0
#define AT_V (2 * 64 * ASTRH)
#define AT_P (AT_V + 2 * 64 * ASTRH)
#define ATTN_SMEM_BYTES ((AT_P + 64 * ASTRH) * 2)   // 46080

__global__ __launch_bounds__(128, 4)
void attn_f16(const __half* __restrict__ q, const __half* __restrict__ k,
              const __half* __restrict__ vt, __half* __restrict__ y)
{
    extern __shared__ char smraw[];
    __half* smh = (__half*)smraw;
    __half* k_s = smh + AT_K;
    __half* v_s = smh + AT_V;
    __half* p_s = smh + AT_P;

    const int h   = blockIdx.x;
    const int qb  = (gridDim.y - 1) - blockIdx.y;     // longest-first
    const int q0  = qb * 64;
    const int tid = threadIdx.x;
    const int w    = tid >> 5;
    const int lane = tid & 31;
    const int gr   = lane >> 2;
    const int tig  = lane & 3;
    const int wrow = w * 16;

    // Q fragments (raw fp16 bits; scale applied post-MMA)
    unsigned aq[4][4];
    {
        const __half* qb_ = q + (size_t)(q0 + wrow) * DIM + h * HD;
#pragma unroll
        for (int ks2 = 0; ks2 < 4; ks2++) {
            aq[ks2][0] = *(const unsigned*)&qb_[(size_t)gr * DIM + ks2 * 16 + 2 * tig];
            aq[ks2][1] = *(const unsigned*)&qb_[(size_t)(gr + 8) * DIM + ks2 * 16 + 2 * tig];
            aq[ks2][2] = *(const unsigned*)&qb_[(size_t)gr * DIM + ks2 * 16 + 8 + 2 * tig];
            aq[ks2][3] = *(const unsigned*)&qb_[(size_t)(gr + 8) * DIM + ks2 * 16 + 8 + 2 * tig];
        }
    }

    float oacc[8][4];
#pragma unroll
    for (int ni = 0; ni < 8; ni++)
#pragma unroll
        for (int r = 0; r < 4; r++) oacc[ni][r] = 0.f;
    float l0 = 0.f, l1 = 0.f;

    const int ar = tid >> 1;
    const int ac = (tid & 1) * 32;
#define LOAD_KV(KB, STG) do {                                                  \
        const __half* kg = k + (size_t)((KB) * 64 + ar) * DIM + h * HD + ac;   \
        const __half* vg = vt + (size_t)(h * HD + ar) * T_LEN + (KB) * 64 + ac;\
        __half* kd = k_s + (STG) * 64 * ASTRH + ar * ASTRH + ac;               \
        __half* vd = v_s + (STG) * 64 * ASTRH + ar * ASTRH + ac;               \
        cp16(kd, kg); cp16(kd + 8, kg + 8); cp16(kd + 16, kg + 16); cp16(kd + 24, kg + 24); \
        cp16(vd, vg); cp16(vd + 8, vg + 8); cp16(vd + 16, vg + 16); cp16(vd + 24, vg + 24); \
    } while (0)

    LOAD_KV(0, 0);
    asm volatile("cp.async.commit_group;\n");

    for (int kb = 0; kb <= qb; kb++) {
        if (kb < qb) {
            LOAD_KV(kb + 1, (kb + 1) & 1);
            asm volatile("cp.async.commit_group;\n");
            asm volatile("cp.async.wait_group 1;\n");
        } else {
            asm volatile("cp.async.wait_group 0;\n");
        }
        __syncthreads();

        const unsigned* Kw = (const unsigned*)(k_s + (kb & 1) * 64 * ASTRH);
        const unsigned* Vw = (const unsigned*)(v_s + (kb & 1) * 64 * ASTRH);

        // ---- S = Q K^T (raw) ----
        float s[8][4];
#pragma unroll
        for (int ni = 0; ni < 8; ni++)
#pragma unroll
            for (int r = 0; r < 4; r++) s[ni][r] = 0.f;

#pragma unroll
        for (int ni = 0; ni < 8; ni++) {
            const unsigned* kr = Kw + (ni * 8 + gr) * ASTRW + tig;
#pragma unroll
            for (int ks2 = 0; ks2 < 4; ks2++) {
                unsigned b[2];
                b[0] = kr[ks2 * 8];
                b[1] = kr[ks2 * 8 + 4];
                mma16(s[ni], aq[ks2], b);
            }
        }

        // ---- fixed-shift softmax (scale 0.125 post-MMA), P as fp16 ----
        const bool diag = (kb == qb);
        const int r0 = wrow + gr, r1 = r0 + 8;
#pragma unroll
        for (int ni = 0; ni < 8; ni++) {
            const int c0 = ni * 8 + 2 * tig;
            float p0 = __expf(fmaf(s[ni][0], 0.125f, -8.f));
            float p1 = __expf(fmaf(s[ni][1], 0.125f, -8.f));
            float p2 = __expf(fmaf(s[ni][2], 0.125f, -8.f));
            float p3 = __expf(fmaf(s[ni][3], 0.125f, -8.f));
            if (diag) {
                if (c0 > r0)     p0 = 0.f;
                if (c0 + 1 > r0) p1 = 0.f;
                if (c0 > r1)     p2 = 0.f;
                if (c0 + 1 > r1) p3 = 0.f;
            }
            l0 += p0 + p1;
            l1 += p2 + p3;
            *(__half2*)&p_s[r0 * ASTRH + c0] = __floats2half2_rn(p0, p1);
            *(__half2*)&p_s[r1 * ASTRH + c0] = __floats2half2_rn(p2, p3);
        }
        __syncwarp();

        // ---- O += P V  (B = V^T tile: [dim][key]) ----
        const unsigned* Pw = (const unsigned*)p_s;
#pragma unroll
        for (int ks2 = 0; ks2 < 4; ks2++) {
            unsigned ap[4];
            ap[0] = Pw[r0 * ASTRW + ks2 * 8 + tig];
            ap[1] = Pw[r1 * ASTRW + ks2 * 8 + tig];
            ap[2] = Pw[r0 * ASTRW + ks2 * 8 + 4 + tig];
            ap[3] = Pw[r1 * ASTRW + ks2 * 8 + 4 + tig];
#pragma unroll
            for (int ni = 0; ni < 8; ni++) {
                const unsigned* vr = Vw + (ni * 8 + gr) * ASTRW + tig;
                unsigned b[2];
                b[0] = vr[ks2 * 8];
                b[1] = vr[ks2 * 8 + 4];
                mma16(oacc[ni], ap, b);
            }
        }
        __syncthreads();
    }

    l0 += __shfl_xor_sync(0xffffffffu, l0, 1);
    l0 += __shfl_xor_sync(0xffffffffu, l0, 2);
    l1 += __shfl_xor_sync(0xffffffffu, l1, 1);
    l1 += __shfl_xor_sync(0xffffffffu, l1, 2);
    const float inv0 = 1.f / l0;
    const float inv1 = 1.f / l1;

    const int r0 = wrow + gr;
#pragma unroll
    for (int ni = 0; ni < 8; ni++) {
        const int c = ni * 8 + 2 * tig;
        *(__half2*)&y[(size_t)(q0 + r0) * DIM + h * HD + c] =
            __floats2half2_rn(oacc[ni][0] * inv0, oacc[ni][1] * inv0);
        *(__half2*)&y[(size_t)(q0 + r0 + 8) * DIM + h * HD + c] =
            __floats2half2_rn(oacc[ni][2] * inv1, oacc[ni][3] * inv1);
    }
}

// ---------------- launch ----------------
extern "C" void kernel_launch(void* const* d_in, const int* in_sizes, int n_in,
                              void* d_out, int out_size)
{
    const float* x    = (const float*)d_in[0];
    const float* vi   = (const float*)d_in[1];
    const float* Wq   = (const float*)d_in[2];
    const float* Wk   = (const float*)d_in[3];
    const float* Wv   = (const float*)d_in[4];
    const float* Wp   = (const float*)d_in[5];
    const float* lamb = (const float*)d_in[6];
    float* out = (float*)d_out;

    __half *xh, *wqh, *wkh, *wvh, *wph, *qh, *kh, *vth, *yh;
    cudaGetSymbolAddress((void**)&xh,  g_xh);
    cudaGetSymbolAddress((void**)&wqh, g_wqh);
    cudaGetSymbolAddress((void**)&wkh, g_wkh);
    cudaGetSymbolAddress((void**)&wvh, g_wvh);
    cudaGetSymbolAddress((void**)&wph, g_wph);
    cudaGetSymbolAddress((void**)&qh,  g_qh);
    cudaGetSymbolAddress((void**)&kh,  g_kh);
    cudaGetSymbolAddress((void**)&vth, g_vth);
    cudaGetSymbolAddress((void**)&yh,  g_yh);

    cudaFuncSetAttribute(gemm_f16, cudaFuncAttributeMaxDynamicSharedMemorySize,
                         GEMM_SMEM_BYTES);
    cudaFuncSetAttribute(attn_f16, cudaFuncAttributeMaxDynamicSharedMemorySize,
                         ATTN_SMEM_BYTES);

    // fp32 -> fp16 conversion of x and all weights
    dim3 gcvt((T_LEN * DIM / 4 + 255) / 256, 5);
    cvt_half_kernel<<<gcvt, 256>>>(x, Wq, Wk, Wv, Wp, xh, wqh, wkh, wvh, wph);

    // fused QKV: z=0/1 -> q/k (norm+rope, half), z=2 -> blended V transposed
    dim3 gqkv(DIM / 128, T_LEN / 128, 3);
    gemm_f16<<<gqkv, 256, GEMM_SMEM_BYTES>>>(xh, wqh, wkh, wvh, qh, kh, vth,
                                             vi, lamb, 1, T_LEN, DIM, DIM);

    // fp16 tensor-core causal attention
    dim3 gattn(NH, T_LEN / 64);
    attn_f16<<<gattn, 128, ATTN_SMEM_BYTES>>>(qh, kh, vth, yh);

    // output projection (fp32 out)
    dim3 gproj(DIM / 128, T_LEN / 128, 1);
    gemm_f16<<<gproj, 256, GEMM_SMEM_BYTES>>>(yh, wph, wph, wph, out, out, out,
                                              nullptr, nullptr, 0, T_LEN, DIM, DIM);
}